// round 11
// baseline (speedup 1.0000x reference)
#include <cuda_runtime.h>
#include <cuda_bf16.h>
#include <math.h>
#include <stdint.h>

#define NHEADS 32
#define QKH    192
#define NOPE   128
#define ROPE   64
#define VH     128
#define KVLORA 512
#define DIM    4096
#define QLORA  1536
#define BATCH  8
#define SEQ    128
#define NTOK   1024
#define NKV    576
#define NQB    6144
#define NKVB   8192

typedef __nv_bfloat16 bf16;

// ---------------- scratch ----------------
__device__ float g_qa2 [2 * NTOK * QLORA];   // split-K partials
__device__ float g_kva2[2 * NTOK * NKV];
__device__ float g_out2[2 * NTOK * DIM];
__device__ float g_ao  [NTOK * DIM];

// int8 quantized operands (h, l limbs) + row scales
__device__ int8_t g_xq_h  [NTOK * DIM],     g_xq_l  [NTOK * DIM];
__device__ int8_t g_qnq_h [NTOK * QLORA],   g_qnq_l [NTOK * QLORA];
__device__ int8_t g_kvnq_h[NTOK * KVLORA],  g_kvnq_l[NTOK * KVLORA];
__device__ int8_t g_aoq_h [NTOK * DIM],     g_aoq_l [NTOK * DIM];
__device__ float  g_sx[NTOK], g_sqn[NTOK], g_skvn[NTOK], g_sao[NTOK];

// int8 weights transposed [N,K] + per-N scales
__device__ int8_t g_wqa_h [QLORA * DIM],    g_wqa_l [QLORA * DIM];
__device__ int8_t g_wkva_h[NKV * DIM],      g_wkva_l[NKV * DIM];
__device__ int8_t g_wqb_h [NQB * QLORA],    g_wqb_l [NQB * QLORA];
__device__ int8_t g_wkvb_h[NKVB * KVLORA],  g_wkvb_l[NKVB * KVLORA];
__device__ int8_t g_wo_h  [DIM * DIM],      g_wo_l  [DIM * DIM];
__device__ float  g_swqa[QLORA], g_swkva[NKV], g_swqb[NQB], g_swkvb[NKVB], g_swo[DIM];

// attention operands (bf16 hi/lo), per (b,h) contiguous
__device__ bf16 g_qp_h[BATCH * NHEADS * SEQ * QKH], g_qp_l[BATCH * NHEADS * SEQ * QKH];
__device__ bf16 g_kp_h[BATCH * NHEADS * SEQ * QKH], g_kp_l[BATCH * NHEADS * SEQ * QKH];
__device__ bf16 g_vT_h[BATCH * NHEADS * VH * SEQ],  g_vT_l[BATCH * NHEADS * VH * SEQ];

// ---------------- helpers ----------------
__device__ __forceinline__ uint32_t smem_u32(const void* p) {
    uint32_t a;
    asm("{ .reg .u64 t; cvta.to.shared.u64 t, %1; cvt.u32.u64 %0, t; }" : "=r"(a) : "l"(p));
    return a;
}
#define CP_ASYNC(dst, src) asm volatile("cp.async.cg.shared.global [%0], [%1], 16;" :: "r"(dst), "l"(src))
#define CP_COMMIT()        asm volatile("cp.async.commit_group;")
#define CP_WAIT1()         asm volatile("cp.async.wait_group 1;")
#define CP_WAIT0()         asm volatile("cp.async.wait_group 0;")

#define LDM_X4(r0, r1, r2, r3, a) \
    asm volatile("ldmatrix.sync.aligned.m8n8.x4.shared.b16 {%0,%1,%2,%3}, [%4];" \
        : "=r"(r0), "=r"(r1), "=r"(r2), "=r"(r3) : "r"(a))

#define MMA(d, a, b0, b1) \
    asm volatile("mma.sync.aligned.m16n8k16.row.col.f32.bf16.bf16.f32 " \
        "{%0,%1,%2,%3}, {%4,%5,%6,%7}, {%8,%9}, {%0,%1,%2,%3};" \
        : "+f"((d)[0]), "+f"((d)[1]), "+f"((d)[2]), "+f"((d)[3]) \
        : "r"((a)[0]), "r"((a)[1]), "r"((a)[2]), "r"((a)[3]), "r"(b0), "r"(b1))

#define IMMA(d, a, b0, b1) \
    asm volatile("mma.sync.aligned.m16n8k32.row.col.s32.s8.s8.s32 " \
        "{%0,%1,%2,%3}, {%4,%5,%6,%7}, {%8,%9}, {%0,%1,%2,%3};" \
        : "+r"((d)[0]), "+r"((d)[1]), "+r"((d)[2]), "+r"((d)[3]) \
        : "r"((a)[0]), "r"((a)[1]), "r"((a)[2]), "r"((a)[3]), "r"(b0), "r"(b1))

__device__ __forceinline__ void split_bf16(float v, unsigned short& h, unsigned short& l) {
    bf16 hb = __float2bfloat16(v);
    h = __bfloat16_as_ushort(hb);
    l = __bfloat16_as_ushort(__float2bfloat16(v - __bfloat162float(hb)));
}
__device__ __forceinline__ void quant2(float q, int& h, int& l) {
    float hf = rintf(q);
    hf = fminf(fmaxf(hf, -127.f), 127.f);
    float lf = rintf((q - hf) * 256.f);
    lf = fminf(fmaxf(lf, -127.f), 127.f);
    h = (int)hf; l = (int)lf;
}

// ---------------- int8 2-limb GEMM: CTA 128x64, BK=64, 8 warps 4x2 -------------
// A: h/l int8 [M,K] + sa[M]; B: h/l int8 [N,K] + sb[N].
// modes: 0 = fp32 C (+ z*M*N partials); 1 = q scatter; 2 = kv scatter.
#define ISTR   80
#define A_PART 10240   // 128*80
#define B_PART 5120    // 64*80
#define ISTAGE 30720   // 2*A_PART + 2*B_PART
#define GEMM_SMEM (2 * ISTAGE)

__global__ void __launch_bounds__(256, 2)
gemm_i8(const int8_t* __restrict__ Ah, const int8_t* __restrict__ Al,
        const int8_t* __restrict__ Bh, const int8_t* __restrict__ Bl,
        const float* __restrict__ sa, const float* __restrict__ sbv,
        float* __restrict__ C, int M, int N, int K, int ksl, int mode) {
    extern __shared__ char smem[];
    const uint32_t sb = smem_u32(smem);
    const int tid = threadIdx.x, lane = tid & 31, wid = tid >> 5;
    const int m0 = blockIdx.y * 128, n0 = blockIdx.x * 64;
    const int wm = wid & 3, wn = wid >> 2;
    const int ks = blockIdx.z * ksl;

    const int8_t* gA[2] = { Ah + (size_t)m0 * K + ks, Al + (size_t)m0 * K + ks };
    const int8_t* gB[2] = { Bh + (size_t)n0 * K + ks, Bl + (size_t)n0 * K + ks };

    // loaders
    const int rowA = tid >> 1, cbA = (tid & 1) * 32;
    const int rowB = tid >> 2, cbB = (tid & 3) * 16;

    int hh[2][4][4], ml[2][4][4];
    #pragma unroll
    for (int i = 0; i < 2; i++)
        #pragma unroll
        for (int j = 0; j < 4; j++)
            #pragma unroll
            for (int k = 0; k < 4; k++) { hh[i][j][k] = 0; ml[i][j][k] = 0; }

    const int kt = ksl >> 6;
    #pragma unroll
    for (int s = 0; s < 2; s++) {
        const int k0 = s * 64;
        const uint32_t st = sb + s * ISTAGE;
        #pragma unroll
        for (int p = 0; p < 2; p++) {
            CP_ASYNC(st + p * A_PART + rowA * ISTR + cbA,      gA[p] + (size_t)rowA * K + k0 + cbA);
            CP_ASYNC(st + p * A_PART + rowA * ISTR + cbA + 16, gA[p] + (size_t)rowA * K + k0 + cbA + 16);
            CP_ASYNC(st + 2 * A_PART + p * B_PART + rowB * ISTR + cbB, gB[p] + (size_t)rowB * K + k0 + cbB);
        }
        CP_COMMIT();
    }

    const int rA = lane & 15, gAx = lane >> 4;
    const uint32_t aoff = (uint32_t)((wm * 32 + rA) * ISTR + gAx * 16);
    const int rB = lane & 7, gBx = lane >> 3;
    const uint32_t boff = (uint32_t)((wn * 32 + (gBx & 1) * 8 + rB) * ISTR + (gBx >> 1) * 16);

    for (int it = 0; it < kt; it++) {
        CP_WAIT1();
        __syncthreads();
        const uint32_t st = sb + (it & 1) * ISTAGE;
        const uint32_t sAh = st, sAl = st + A_PART;
        const uint32_t sBh = st + 2 * A_PART, sBl = st + 2 * A_PART + B_PART;
        #pragma unroll
        for (int k2 = 0; k2 < 2; k2++) {
            const uint32_t ko = k2 * 32;
            uint32_t ah[2][4], al[2][4];
            #pragma unroll
            for (int mt = 0; mt < 2; mt++) {
                LDM_X4(ah[mt][0], ah[mt][1], ah[mt][2], ah[mt][3], sAh + aoff + mt * (16 * ISTR) + ko);
                LDM_X4(al[mt][0], al[mt][1], al[mt][2], al[mt][3], sAl + aoff + mt * (16 * ISTR) + ko);
            }
            #pragma unroll
            for (int ngp = 0; ngp < 2; ngp++) {
                uint32_t bhf[4], blf[4];
                LDM_X4(bhf[0], bhf[1], bhf[2], bhf[3], sBh + boff + ngp * (16 * ISTR) + ko);
                LDM_X4(blf[0], blf[1], blf[2], blf[3], sBl + boff + ngp * (16 * ISTR) + ko);
                #pragma unroll
                for (int g = 0; g < 2; g++)
                    #pragma unroll
                    for (int mt = 0; mt < 2; mt++)
                        IMMA(hh[mt][ngp * 2 + g], ah[mt], bhf[g], bhf[2 + g]);
                #pragma unroll
                for (int g = 0; g < 2; g++)
                    #pragma unroll
                    for (int mt = 0; mt < 2; mt++)
                        IMMA(ml[mt][ngp * 2 + g], ah[mt], blf[g], blf[2 + g]);
                #pragma unroll
                for (int g = 0; g < 2; g++)
                    #pragma unroll
                    for (int mt = 0; mt < 2; mt++)
                        IMMA(ml[mt][ngp * 2 + g], al[mt], bhf[g], bhf[2 + g]);
            }
        }
        __syncthreads();
        const int kn = it + 2;
        if (kn < kt) {
            const int k0 = kn * 64;
            const uint32_t s2 = sb + (it & 1) * ISTAGE;
            #pragma unroll
            for (int p = 0; p < 2; p++) {
                CP_ASYNC(s2 + p * A_PART + rowA * ISTR + cbA,      gA[p] + (size_t)rowA * K + k0 + cbA);
                CP_ASYNC(s2 + p * A_PART + rowA * ISTR + cbA + 16, gA[p] + (size_t)rowA * K + k0 + cbA + 16);
                CP_ASYNC(s2 + 2 * A_PART + p * B_PART + rowB * ISTR + cbB, gB[p] + (size_t)rowB * K + k0 + cbB);
            }
        }
        CP_COMMIT();
    }

    const float i256 = 1.f / 256.f;
    if (mode == 0) {
        float* Cz = C + (size_t)blockIdx.z * M * N;
        #pragma unroll
        for (int mt = 0; mt < 2; mt++) {
            const int r0 = m0 + wm * 32 + mt * 16 + (lane >> 2);
            const float sa0 = sa[r0], sa1 = sa[r0 + 8];
            #pragma unroll
            for (int nt = 0; nt < 4; nt++) {
                const int c0 = n0 + wn * 32 + nt * 8 + (lane & 3) * 2;
                if (c0 < N) {
                    const float sb0 = sbv[c0], sb1 = sbv[c0 + 1];
                    float v00 = sa0 * sb0 * ((float)hh[mt][nt][0] + (float)ml[mt][nt][0] * i256);
                    float v01 = sa0 * sb1 * ((float)hh[mt][nt][1] + (float)ml[mt][nt][1] * i256);
                    float v10 = sa1 * sb0 * ((float)hh[mt][nt][2] + (float)ml[mt][nt][2] * i256);
                    float v11 = sa1 * sb1 * ((float)hh[mt][nt][3] + (float)ml[mt][nt][3] * i256);
                    *(float2*)&Cz[(size_t)r0 * N + c0] = make_float2(v00, v01);
                    *(float2*)&Cz[(size_t)(r0 + 8) * N + c0] = make_float2(v10, v11);
                }
            }
        }
    } else if (mode == 1) {
        #pragma unroll
        for (int mt = 0; mt < 2; mt++) {
            const int r0 = m0 + wm * 32 + mt * 16 + (lane >> 2);
            const float sa0 = sa[r0], sa1 = sa[r0 + 8];
            const int b = r0 >> 7, t = r0 & 127;
            #pragma unroll
            for (int nt = 0; nt < 4; nt++) {
                const int c0 = n0 + wn * 32 + nt * 8 + (lane & 3) * 2;
                const float sb0 = sbv[c0], sb1 = sbv[c0 + 1];
                const int h = c0 / 192, d = c0 - h * 192;
                const size_t base = ((size_t)((b * 32 + h) * 128 + t)) * 192 + d;
                float v00 = sa0 * sb0 * ((float)hh[mt][nt][0] + (float)ml[mt][nt][0] * i256);
                float v01 = sa0 * sb1 * ((float)hh[mt][nt][1] + (float)ml[mt][nt][1] * i256);
                float v10 = sa1 * sb0 * ((float)hh[mt][nt][2] + (float)ml[mt][nt][2] * i256);
                float v11 = sa1 * sb1 * ((float)hh[mt][nt][3] + (float)ml[mt][nt][3] * i256);
                unsigned short h0, l0, h1, l1;
                split_bf16(v00, h0, l0); split_bf16(v01, h1, l1);
                *(uint32_t*)((unsigned short*)g_qp_h + base) = h0 | ((uint32_t)h1 << 16);
                *(uint32_t*)((unsigned short*)g_qp_l + base) = l0 | ((uint32_t)l1 << 16);
                split_bf16(v10, h0, l0); split_bf16(v11, h1, l1);
                *(uint32_t*)((unsigned short*)g_qp_h + base + 8 * 192) = h0 | ((uint32_t)h1 << 16);
                *(uint32_t*)((unsigned short*)g_qp_l + base + 8 * 192) = l0 | ((uint32_t)l1 << 16);
            }
        }
    } else {
        const int hd = n0 >> 8;
        const int b = m0 >> 7;
        if ((n0 & 255) < 128) {
            // K-nope block
            #pragma unroll
            for (int mt = 0; mt < 2; mt++) {
                const int r0 = m0 + wm * 32 + mt * 16 + (lane >> 2);
                const float sa0 = sa[r0], sa1 = sa[r0 + 8];
                const int t = r0 & 127;
                #pragma unroll
                for (int nt = 0; nt < 4; nt++) {
                    const int d = (n0 & 255) + wn * 32 + nt * 8 + (lane & 3) * 2;
                    const int c0 = n0 + wn * 32 + nt * 8 + (lane & 3) * 2;
                    const float sb0 = sbv[c0], sb1 = sbv[c0 + 1];
                    const size_t base = ((size_t)((b * 32 + hd) * 128 + t)) * 192 + d;
                    float v00 = sa0 * sb0 * ((float)hh[mt][nt][0] + (float)ml[mt][nt][0] * i256);
                    float v01 = sa0 * sb1 * ((float)hh[mt][nt][1] + (float)ml[mt][nt][1] * i256);
                    float v10 = sa1 * sb0 * ((float)hh[mt][nt][2] + (float)ml[mt][nt][2] * i256);
                    float v11 = sa1 * sb1 * ((float)hh[mt][nt][3] + (float)ml[mt][nt][3] * i256);
                    unsigned short h0, l0, h1, l1;
                    split_bf16(v00, h0, l0); split_bf16(v01, h1, l1);
                    *(uint32_t*)((unsigned short*)g_kp_h + base) = h0 | ((uint32_t)h1 << 16);
                    *(uint32_t*)((unsigned short*)g_kp_l + base) = l0 | ((uint32_t)l1 << 16);
                    split_bf16(v10, h0, l0); split_bf16(v11, h1, l1);
                    *(uint32_t*)((unsigned short*)g_kp_h + base + 8 * 192) = h0 | ((uint32_t)h1 << 16);
                    *(uint32_t*)((unsigned short*)g_kp_l + base + 8 * 192) = l0 | ((uint32_t)l1 << 16);
                }
            }
        } else {
            // V block: transpose through smem
            __syncthreads();
            float* T = (float*)smem;  // [64 dv][132]
            #pragma unroll
            for (int mt = 0; mt < 2; mt++) {
                const int tl = wm * 32 + mt * 16 + (lane >> 2);
                const float sa0 = sa[m0 + tl], sa1 = sa[m0 + tl + 8];
                #pragma unroll
                for (int nt = 0; nt < 4; nt++) {
                    const int dv = wn * 32 + nt * 8 + (lane & 3) * 2;
                    const int c0 = n0 + dv;
                    const float sb0 = sbv[c0], sb1 = sbv[c0 + 1];
                    T[dv * 132 + tl]           = sa0 * sb0 * ((float)hh[mt][nt][0] + (float)ml[mt][nt][0] * i256);
                    T[(dv + 1) * 132 + tl]     = sa0 * sb1 * ((float)hh[mt][nt][1] + (float)ml[mt][nt][1] * i256);
                    T[dv * 132 + tl + 8]       = sa1 * sb0 * ((float)hh[mt][nt][2] + (float)ml[mt][nt][2] * i256);
                    T[(dv + 1) * 132 + tl + 8] = sa1 * sb1 * ((float)hh[mt][nt][3] + (float)ml[mt][nt][3] * i256);
                }
            }
            __syncthreads();
            const int dvb = (n0 & 255) - 128;
            const size_t vb = ((size_t)((b * 32 + hd) * 128)) * 128;
            for (int i = tid; i < 2048; i += 256) {
                const int dv = i >> 5, tq = (i & 31) * 4;
                const float* r = T + dv * 132 + tq;
                unsigned short h0, l0, h1, l1, h2, l2, h3, l3;
                split_bf16(r[0], h0, l0); split_bf16(r[1], h1, l1);
                split_bf16(r[2], h2, l2); split_bf16(r[3], h3, l3);
                const size_t o = vb + (size_t)(dvb + dv) * 128 + tq;
                *(uint2*)((unsigned short*)g_vT_h + o) = make_uint2(h0 | ((uint32_t)h1 << 16), h2 | ((uint32_t)h3 << 16));
                *(uint2*)((unsigned short*)g_vT_l + o) = make_uint2(l0 | ((uint32_t)l1 << 16), l2 | ((uint32_t)l3 << 16));
            }
        }
    }
}

// ---------------- quant / pack kernels ----------------
__global__ void __launch_bounds__(256) wmax(const float* __restrict__ W, float* __restrict__ s,
                                            int K, int N) {
    __shared__ float red[256];
    const int col = blockIdx.x * 32 + (threadIdx.x & 31);
    const int part = threadIdx.x >> 5;
    float m = 0.f;
    for (int k = part; k < K; k += 8) m = fmaxf(m, fabsf(W[(size_t)k * N + col]));
    red[threadIdx.x] = m;
    __syncthreads();
    if (part == 0) {
        #pragma unroll
        for (int p = 1; p < 8; p++) m = fmaxf(m, red[p * 32 + threadIdx.x]);
        s[col] = fmaxf(m, 1e-20f) * (1.f / 127.f);
    }
}

// transpose + 2-limb quantize: W[K,N] fp32 -> h/l [N,K] int8 (N%32==0, K%128==0)
__global__ void __launch_bounds__(256) wquant(const float* __restrict__ W, const float* __restrict__ s,
                                              int8_t* __restrict__ oh, int8_t* __restrict__ ol,
                                              int K, int N) {
    __shared__ float tile[128][33];
    const int n0 = blockIdx.x * 32, k0 = blockIdx.y * 128;
    const int tid = threadIdx.x;
    const int lr = tid >> 3, lc = (tid & 7) * 4;
    #pragma unroll
    for (int j = 0; j < 4; j++) {
        const int k = k0 + lr + j * 32;
        float4 v = *(const float4*)(W + (size_t)k * N + n0 + lc);
        tile[lr + j * 32][lc] = v.x; tile[lr + j * 32][lc + 1] = v.y;
        tile[lr + j * 32][lc + 2] = v.z; tile[lr + j * 32][lc + 3] = v.w;
    }
    __syncthreads();
    const int nl = tid >> 3, kk = (tid & 7) * 16;
    const float is = 1.f / s[n0 + nl];
    uint32_t ph[4], pl[4];
    #pragma unroll
    for (int w4 = 0; w4 < 4; w4++) {
        uint32_t a = 0, c = 0;
        #pragma unroll
        for (int j = 0; j < 4; j++) {
            int h, l;
            quant2(tile[kk + w4 * 4 + j][nl] * is, h, l);
            a |= ((uint32_t)(uint8_t)(int8_t)h) << (j * 8);
            c |= ((uint32_t)(uint8_t)(int8_t)l) << (j * 8);
        }
        ph[w4] = a; pl[w4] = c;
    }
    const size_t ob = (size_t)(n0 + nl) * K + k0 + kk;
    *(uint4*)(oh + ob) = make_uint4(ph[0], ph[1], ph[2], ph[3]);
    *(uint4*)(ol + ob) = make_uint4(pl[0], pl[1], pl[2], pl[3]);
}

// per-row 2-limb quantization of a fp32 matrix (one block per row)
__global__ void __launch_bounds__(256) act_quant(const float* __restrict__ in,
                                                 int8_t* __restrict__ oh, int8_t* __restrict__ ol,
                                                 float* __restrict__ srow, int ncols) {
    __shared__ float red[256];
    const int row = blockIdx.x;
    const float* p = in + (size_t)row * ncols;
    float mx = 0.f;
    for (int i = threadIdx.x; i < ncols; i += 256) mx = fmaxf(mx, fabsf(p[i]));
    red[threadIdx.x] = mx; __syncthreads();
    for (int off = 128; off > 0; off >>= 1) {
        if (threadIdx.x < off) red[threadIdx.x] = fmaxf(red[threadIdx.x], red[threadIdx.x + off]);
        __syncthreads();
    }
    const float sc = fmaxf(red[0], 1e-20f) * (1.f / 127.f);
    if (threadIdx.x == 0) srow[row] = sc;
    const float is = 1.f / sc;
    for (int i = threadIdx.x; i < ncols; i += 256) {
        int h, l;
        quant2(p[i] * is, h, l);
        oh[(size_t)row * ncols + i] = (int8_t)h;
        ol[(size_t)row * ncols + i] = (int8_t)l;
    }
}

// rmsnorm of (P0+P1) row then 2-limb quantize
__global__ void __launch_bounds__(256) rmsnorm_quant(const float* __restrict__ in,
                                                     const float* __restrict__ w,
                                                     int8_t* __restrict__ oh, int8_t* __restrict__ ol,
                                                     float* __restrict__ srow,
                                                     int ncols, int ld, int poff) {
    __shared__ float red[256];
    const int row = blockIdx.x;
    const float* p0 = in + (size_t)row * ld;
    const float* p1 = p0 + (size_t)poff;
    float ss = 0.f;
    for (int i = threadIdx.x; i < ncols; i += 256) { float v = p0[i] + p1[i]; ss += v * v; }
    red[threadIdx.x] = ss; __syncthreads();
    for (int off = 128; off > 0; off >>= 1) {
        if (threadIdx.x < off) red[threadIdx.x] += red[threadIdx.x + off];
        __syncthreads();
    }
    const float scale = rsqrtf(red[0] / (float)ncols + 1e-6f);
    __syncthreads();
    float mx = 0.f;
    for (int i = threadIdx.x; i < ncols; i += 256)
        mx = fmaxf(mx, fabsf((p0[i] + p1[i]) * scale * w[i]));
    red[threadIdx.x] = mx; __syncthreads();
    for (int off = 128; off > 0; off >>= 1) {
        if (threadIdx.x < off) red[threadIdx.x] = fmaxf(red[threadIdx.x], red[threadIdx.x + off]);
        __syncthreads();
    }
    const float sc = fmaxf(red[0], 1e-20f) * (1.f / 127.f);
    if (threadIdx.x == 0) srow[row] = sc;
    const float is = 1.f / sc;
    for (int i = threadIdx.x; i < ncols; i += 256) {
        int h, l;
        quant2((p0[i] + p1[i]) * scale * w[i] * is, h, l);
        oh[(size_t)row * ncols + i] = (int8_t)h;
        ol[(size_t)row * ncols + i] = (int8_t)l;
    }
}

// rmsnorm(kv_lat)+quant, plus roped k_pe broadcast into g_kp (bf16)
__global__ void __launch_bounds__(256) kv_post_quant(const float* __restrict__ w,
                                                     const float* __restrict__ freqs) {
    __shared__ float red[256];
    const int tg = blockIdx.x;
    const int b = tg >> 7, s = tg & 127;
    const float* p0 = g_kva2 + (size_t)tg * NKV;
    const float* p1 = p0 + (size_t)NTOK * NKV;
    float ss = 0.f;
    for (int i = threadIdx.x; i < KVLORA; i += 256) { float v = p0[i] + p1[i]; ss += v * v; }
    red[threadIdx.x] = ss; __syncthreads();
    for (int off = 128; off > 0; off >>= 1) {
        if (threadIdx.x < off) red[threadIdx.x] += red[threadIdx.x + off];
        __syncthreads();
    }
    const float scale = rsqrtf(red[0] / (float)KVLORA + 1e-6f);
    __syncthreads();
    float mx = 0.f;
    for (int i = threadIdx.x; i < KVLORA; i += 256)
        mx = fmaxf(mx, fabsf((p0[i] + p1[i]) * scale * w[i]));
    red[threadIdx.x] = mx; __syncthreads();
    for (int off = 128; off > 0; off >>= 1) {
        if (threadIdx.x < off) red[threadIdx.x] = fmaxf(red[threadIdx.x], red[threadIdx.x + off]);
        __syncthreads();
    }
    const float sc = fmaxf(red[0], 1e-20f) * (1.f / 127.f);
    if (threadIdx.x == 0) g_skvn[tg] = sc;
    const float is = 1.f / sc;
    for (int i = threadIdx.x; i < KVLORA; i += 256) {
        int h, l;
        quant2((p0[i] + p1[i]) * scale * w[i] * is, h, l);
        g_kvnq_h[(size_t)tg * KVLORA + i] = (int8_t)h;
        g_kvnq_l[(size_t)tg * KVLORA + i] = (int8_t)l;
    }
    if (threadIdx.x < ROPE) {
        const int d = threadIdx.x;
        unsigned short h, l;
        split_bf16((p0[KVLORA + d] + p1[KVLORA + d]) * freqs[s * (ROPE / 2) + (d >> 1)], h, l);
        #pragma unroll 4
        for (int hh2 = 0; hh2 < NHEADS; hh2++) {
            const size_t a = ((size_t)((b * 32 + hh2) * 128 + s)) * 192 + 128 + d;
            ((unsigned short*)g_kp_h)[a] = h;
            ((unsigned short*)g_kp_l)[a] = l;
        }
    }
}

__global__ void __launch_bounds__(256) add2(const float* __restrict__ a,
                                            const float* __restrict__ b,
                                            float* __restrict__ o, int n) {
    const int i = (blockIdx.x * 256 + threadIdx.x) * 4;
    if (i >= n) return;
    float4 va = *(const float4*)(a + i);
    float4 vb = *(const float4*)(b + i);
    *(float4*)(o + i) = make_float4(va.x + vb.x, va.y + vb.y, va.z + vb.z, va.w + vb.w);
}

// ---------------- fused flash attention per (b,h) (bf16, as R9; fp32 out) -------
#define SROW    40
#define PART_B  (128 * SROW * 2)
#define STAGE_B (4 * PART_B)
#define VBASE  81920
#define PLBASE 34816
#define REDOFF 122880
#define PSTR   136
#define FLASH_SMEM 124928

__global__ void __launch_bounds__(256, 1) flash_attn() {
    extern __shared__ char smem[];
    const uint32_t sb = smem_u32(smem);
    const int tid = threadIdx.x, lane = tid & 31, wid = tid >> 5;
    const int wm = wid & 3, wn = wid >> 2;
    const int bh = blockIdx.x, b = bh >> 5, h = bh & 31;

    const bf16* gqh = g_qp_h + (size_t)bh * SEQ * QKH;
    const bf16* gql = g_qp_l + (size_t)bh * SEQ * QKH;
    const bf16* gkh = g_kp_h + (size_t)bh * SEQ * QKH;
    const bf16* gkl = g_kp_l + (size_t)bh * SEQ * QKH;
    const bf16* gvh = g_vT_h + (size_t)bh * VH * SEQ;
    const bf16* gvl = g_vT_l + (size_t)bh * VH * SEQ;
    const bf16* gp[4] = { gqh, gql, gkh, gkl };

    const int r0c = tid >> 2, c0c = (tid & 3) * 8;

    #pragma unroll
    for (int s = 0; s < 2; s++) {
        const int k0 = s * 32;
        const uint32_t st = sb + s * STAGE_B;
        #pragma unroll
        for (int p = 0; p < 4; p++) {
            CP_ASYNC(st + p * PART_B + r0c * 80 + c0c * 2, gp[p] + (size_t)r0c * QKH + k0 + c0c);
            CP_ASYNC(st + p * PART_B + (r0c + 64) * 80 + c0c * 2, gp[p] + (size_t)(r0c + 64) * QKH + k0 + c0c);
        }
        const uint32_t vst = sb + VBASE + s * 20480;
        CP_ASYNC(vst + r0c * 80 + c0c * 2, gvh + (size_t)r0c * SEQ + k0 + c0c);
        CP_ASYNC(vst + (r0c + 64) * 80 + c0c * 2, gvh + (size_t)(r0c + 64) * SEQ + k0 + c0c);
        CP_ASYNC(vst + 10240 + r0c * 80 + c0c * 2, gvl + (size_t)r0c * SEQ + k0 + c0c);
        CP_ASYNC(vst + 10240 + (r0c + 64) * 80 + c0c * 2, gvl + (size_t)(r0c + 64) * SEQ + k0 + c0c);
        CP_COMMIT();
    }

    const int rA = lane & 15, gA = lane >> 4;
    const uint32_t aoff = (uint32_t)(((wm * 32 + rA) * SROW + gA * 8) * 2);
    const int rB = lane & 7, gB = lane >> 3;
    const uint32_t boff = (uint32_t)(((wn * 64 + (gB & 1) * 8 + rB) * SROW + (gB >> 1) * 8) * 2);

    float acc[2][8][4];
    #pragma unroll
    for (int i = 0; i < 2; i++)
        #pragma unroll
        for (int j = 0; j < 8; j++)
            #pragma unroll
            for (int k = 0; k < 4; k++) acc[i][j][k] = 0.f;

    for (int it = 0; it < 6; it++) {
        CP_WAIT1();
        __syncthreads();
        const uint32_t st = sb + (it & 1) * STAGE_B;
        const uint32_t sAh = st, sAl = st + PART_B, sBh = st + 2 * PART_B, sBl = st + 3 * PART_B;
        #pragma unroll
        for (int k2 = 0; k2 < 2; k2++) {
            const uint32_t ko = k2 * 32;
            uint32_t ah[2][4], al[2][4];
            #pragma unroll
            for (int mt = 0; mt < 2; mt++) {
                LDM_X4(ah[mt][0], ah[mt][1], ah[mt][2], ah[mt][3], sAh + aoff + mt * (16 * SROW * 2) + ko);
                LDM_X4(al[mt][0], al[mt][1], al[mt][2], al[mt][3], sAl + aoff + mt * (16 * SROW * 2) + ko);
            }
            #pragma unroll
            for (int ng = 0; ng < 4; ng++) {
                uint32_t bh2[4], bl2[4];
                LDM_X4(bh2[0], bh2[1], bh2[2], bh2[3], sBh + boff + ng * (16 * SROW * 2) + ko);
                LDM_X4(bl2[0], bl2[1], bl2[2], bl2[3], sBl + boff + ng * (16 * SROW * 2) + ko);
                #pragma unroll
                for (int mt = 0; mt < 2; mt++) {
                    #pragma unroll
                    for (int hh = 0; hh < 2; hh++) {
                        float* d = acc[mt][ng * 2 + hh];
                        MMA(d, ah[mt], bh2[hh], bh2[2 + hh]);
                        MMA(d, ah[mt], bl2[hh], bl2[2 + hh]);
                        MMA(d, al[mt], bh2[hh], bh2[2 + hh]);
                    }
                }
            }
        }
        __syncthreads();
        const int kn = it + 2;
        if (kn < 6) {
            const int k0 = kn * 32;
            const uint32_t s2 = sb + (it & 1) * STAGE_B;
            #pragma unroll
            for (int p = 0; p < 4; p++) {
                CP_ASYNC(s2 + p * PART_B + r0c * 80 + c0c * 2, gp[p] + (size_t)r0c * QKH + k0 + c0c);
                CP_ASYNC(s2 + p * PART_B + (r0c + 64) * 80 + c0c * 2, gp[p] + (size_t)(r0c + 64) * QKH + k0 + c0c);
            }
        }
        CP_COMMIT();
    }
    CP_WAIT0();
    __syncthreads();

    float* RMAX = (float*)(smem + REDOFF);
    float* RSUM = (float*)(smem + REDOFF + 1024);
    const float scl = 0.07216878364870323f;
    const int rbase = wm * 32 + (lane >> 2);
    const int cbase = wn * 64 + (lane & 3) * 2;

    #pragma unroll
    for (int mt = 0; mt < 2; mt++)
        #pragma unroll
        for (int nt = 0; nt < 8; nt++)
            #pragma unroll
            for (int k = 0; k < 4; k++) {
                const int r = rbase + mt * 16 + (k >> 1) * 8;
                const int c = cbase + nt * 8 + (k & 1);
                float v = acc[mt][nt][k] * scl;
                acc[mt][nt][k] = (c > r) ? -INFINITY : v;
            }

    #pragma unroll
    for (int mt = 0; mt < 2; mt++)
        #pragma unroll
        for (int hf = 0; hf < 2; hf++) {
            float m = -INFINITY;
            #pragma unroll
            for (int nt = 0; nt < 8; nt++)
                m = fmaxf(m, fmaxf(acc[mt][nt][hf * 2], acc[mt][nt][hf * 2 + 1]));
            m = fmaxf(m, __shfl_xor_sync(0xffffffffu, m, 1));
            m = fmaxf(m, __shfl_xor_sync(0xffffffffu, m, 2));
            if ((lane & 3) == 0) RMAX[wn * 128 + rbase + mt * 16 + hf * 8] = m;
        }
    __syncthreads();
    #pragma unroll
    for (int mt = 0; mt < 2; mt++)
        #pragma unroll
        for (int hf = 0; hf < 2; hf++) {
            const int r = rbase + mt * 16 + hf * 8;
            const float m = fmaxf(RMAX[r], RMAX[128 + r]);
            float s = 0.f;
            #pragma unroll
            for (int nt = 0; nt < 8; nt++) {
                float p0 = expf(acc[mt][nt][hf * 2] - m);
                float p1 = expf(acc[mt][nt][hf * 2 + 1] - m);
                acc[mt][nt][hf * 2] = p0; acc[mt][nt][hf * 2 + 1] = p1;
                s += p0 + p1;
            }
            s += __shfl_xor_sync(0xffffffffu, s, 1);
            s += __shfl_xor_sync(0xffffffffu, s, 2);
            if ((lane & 3) == 0) RSUM[wn * 128 + r] = s;
        }
    #pragma unroll
    for (int mt = 0; mt < 2; mt++)
        #pragma unroll
        for (int nt = 0; nt < 8; nt++)
            #pragma unroll
            for (int hf = 0; hf < 2; hf++) {
                const int r = rbase + mt * 16 + hf * 8;
                const int c = cbase + nt * 8;
                unsigned short h0, l0, h1, l1;
                split_bf16(acc[mt][nt][hf * 2], h0, l0);
                split_bf16(acc[mt][nt][hf * 2 + 1], h1, l1);
                *(uint32_t*)(smem + (r * PSTR + c) * 2) = h0 | ((uint32_t)h1 << 16);
                *(uint32_t*)(smem + PLBASE + (r * PSTR + c) * 2) = l0 | ((uint32_t)l1 << 16);
            }
    __syncthreads();

    const uint32_t aoffP = (uint32_t)(((wm * 32 + rA) * PSTR + gA * 8) * 2);
    float o[2][8][4];
    #pragma unroll
    for (int i = 0; i < 2; i++)
        #pragma unroll
        for (int j = 0; j < 8; j++)
            #pragma unroll
            for (int k = 0; k < 4; k++) o[i][j][k] = 0.f;

    for (int it = 0; it < 4; it++) {
        CP_WAIT1();
        __syncthreads();
        const uint32_t vst = sb + VBASE + (it & 1) * 20480;
        #pragma unroll
        for (int k2 = 0; k2 < 2; k2++) {
            const uint32_t kP = (it * 32 + k2 * 16) * 2;
            const uint32_t kV = k2 * 32;
            uint32_t ph[2][4], pl[2][4];
            #pragma unroll
            for (int mt = 0; mt < 2; mt++) {
                LDM_X4(ph[mt][0], ph[mt][1], ph[mt][2], ph[mt][3], sb + aoffP + mt * (16 * PSTR * 2) + kP);
                LDM_X4(pl[mt][0], pl[mt][1], pl[mt][2], pl[mt][3], sb + PLBASE + aoffP + mt * (16 * PSTR * 2) + kP);
            }
            #pragma unroll
            for (int ng = 0; ng < 4; ng++) {
                uint32_t vh[4], vl[4];
                LDM_X4(vh[0], vh[1], vh[2], vh[3], vst + boff + ng * (16 * SROW * 2) + kV);
                LDM_X4(vl[0], vl[1], vl[2], vl[3], vst + 10240 + boff + ng * (16 * SROW * 2) + kV);
                #pragma unroll
                for (int mt = 0; mt < 2; mt++) {
                    #pragma unroll
                    for (int hh = 0; hh < 2; hh++) {
                        float* d = o[mt][ng * 2 + hh];
                        MMA(d, ph[mt], vh[hh], vh[2 + hh]);
                        MMA(d, ph[mt], vl[hh], vl[2 + hh]);
                        MMA(d, pl[mt], vh[hh], vh[2 + hh]);
                    }
                }
            }
        }
        __syncthreads();
        const int kn = it + 2;
        if (kn < 4) {
            const int k0 = kn * 32;
            const uint32_t v2 = sb + VBASE + (it & 1) * 20480;
            CP_ASYNC(v2 + r0c * 80 + c0c * 2, gvh + (size_t)r0c * SEQ + k0 + c0c);
            CP_ASYNC(v2 + (r0c + 64) * 80 + c0c * 2, gvh + (size_t)(r0c + 64) * SEQ + k0 + c0c);
            CP_ASYNC(v2 + 10240 + r0c * 80 + c0c * 2, gvl + (size_t)r0c * SEQ + k0 + c0c);
            CP_ASYNC(v2 + 10240 + (r0c + 64) * 80 + c0c * 2, gvl + (size_t)(r0c + 64) * SEQ + k0 + c0c);
        }
        CP_COMMIT();
    }

    #pragma unroll
    for (int mt = 0; mt < 2; mt++) {
        float inv[2];
        #pragma unroll
        for (int hf = 0; hf < 2; hf++) {
            const int r = rbase + mt * 16 + hf * 8;
            inv[hf] = 1.f / (RSUM[r] + RSUM[128 + r]);
        }
        #pragma unroll
        for (int nt = 0; nt < 8; nt++) {
            const int c = cbase + nt * 8;
            #pragma unroll
            for (int hf = 0; hf < 2; hf++) {
                const int r = rbase + mt * 16 + hf * 8;
                const size_t off = (size_t)(b * SEQ + r) * DIM + h * VH + c;
                *(float2*)(g_ao + off) = make_float2(o[mt][nt][hf * 2] * inv[hf],
                                                     o[mt][nt][hf * 2 + 1] * inv[hf]);
            }
        }
    }
}

// ---------------- launch ----------------
extern "C" void kernel_launch(void* const* d_in, const int* in_sizes, int n_in,
                              void* d_out, int out_size) {
    const float* x       = (const float*)d_in[0];
    const float* freqs   = (const float*)d_in[1];
    const float* wq_a    = (const float*)d_in[2];
    const float* q_norm  = (const float*)d_in[3];
    const float* wq_b    = (const float*)d_in[4];
    const float* wkv_a   = (const float*)d_in[5];
    const float* kv_norm = (const float*)d_in[6];
    const float* wkv_b   = (const float*)d_in[7];
    const float* wo      = (const float*)d_in[8];
    float* out = (float*)d_out;

    cudaFuncSetAttribute(gemm_i8, cudaFuncAttributeMaxDynamicSharedMemorySize, GEMM_SMEM);
    cudaFuncSetAttribute(flash_attn, cudaFuncAttributeMaxDynamicSharedMemorySize, FLASH_SMEM);

    float *qa2, *kva2, *out2, *ao;
    float *sx, *sqn, *skvn, *sao, *swqa, *swkva, *swqb, *swkvb, *swo;
    int8_t *xqh, *xql, *qnh, *qnl, *kvnh, *kvnl, *aoh, *aol;
    int8_t *wqah, *wqal, *wkvah, *wkval, *wqbh, *wqbl, *wkvbh, *wkvbl, *woh, *wol;
    cudaGetSymbolAddress((void**)&qa2,  g_qa2);
    cudaGetSymbolAddress((void**)&kva2, g_kva2);
    cudaGetSymbolAddress((void**)&out2, g_out2);
    cudaGetSymbolAddress((void**)&ao,   g_ao);
    cudaGetSymbolAddress((void**)&sx,   g_sx);   cudaGetSymbolAddress((void**)&sqn,  g_sqn);
    cudaGetSymbolAddress((void**)&skvn, g_skvn); cudaGetSymbolAddress((void**)&sao,  g_sao);
    cudaGetSymbolAddress((void**)&swqa, g_swqa); cudaGetSymbolAddress((void**)&swkva, g_swkva);
    cudaGetSymbolAddress((void**)&swqb, g_swqb); cudaGetSymbolAddress((void**)&swkvb, g_swkvb);
    cudaGetSymbolAddress((void**)&swo,  g_swo);
    cudaGetSymbolAddress((void**)&xqh,  g_xq_h);  cudaGetSymbolAddress((void**)&xql,  g_xq_l);
    cudaGetSymbolAddress((void**)&qnh,  g_qnq_h); cudaGetSymbolAddress((void**)&qnl,  g_qnq_l);
    cudaGetSymbolAddress((void**)&kvnh, g_kvnq_h); cudaGetSymbolAddress((void**)&kvnl, g_kvnq_l);
    cudaGetSymbolAddress((void**)&aoh,  g_aoq_h); cudaGetSymbolAddress((void**)&aol,  g_aoq_l);
    cudaGetSymbolAddress((void**)&wqah,  g_wqa_h);  cudaGetSymbolAddress((void**)&wqal,  g_wqa_l);
    cudaGetSymbolAddress((void**)&wkvah, g_wkva_h); cudaGetSymbolAddress((void**)&wkval, g_wkva_l);
    cudaGetSymbolAddress((void**)&wqbh,  g_wqb_h);  cudaGetSymbolAddress((void**)&wqbl,  g_wqb_l);
    cudaGetSymbolAddress((void**)&wkvbh, g_wkvb_h); cudaGetSymbolAddress((void**)&wkvbl, g_wkvb_l);
    cudaGetSymbolAddress((void**)&woh,   g_wo_h);   cudaGetSymbolAddress((void**)&wol,   g_wo_l);

    // #1-3 prep, #4 = int8 gemm qa (ncu profiled slot)
    wmax<<<QLORA / 32, 256>>>(wq_a, swqa, DIM, QLORA);
    wquant<<<dim3(QLORA / 32, DIM / 128), 256>>>(wq_a, swqa, wqah, wqal, DIM, QLORA);
    act_quant<<<NTOK, 256>>>(x, xqh, xql, sx, DIM);

    gemm_i8<<<dim3(QLORA / 64, NTOK / 128, 2), 256, GEMM_SMEM>>>(
        xqh, xql, wqah, wqal, sx, swqa, qa2, NTOK, QLORA, DIM, DIM / 2, 0);

    wmax<<<NKV / 32, 256>>>(wkv_a, swkva, DIM, NKV);
    wquant<<<dim3(NKV / 32, DIM / 128), 256>>>(wkv_a, swkva, wkvah, wkval, DIM, NKV);
    gemm_i8<<<dim3(NKV / 64, NTOK / 128, 2), 256, GEMM_SMEM>>>(
        xqh, xql, wkvah, wkval, sx, swkva, kva2, NTOK, NKV, DIM, DIM / 2, 0);

    rmsnorm_quant<<<NTOK, 256>>>(qa2, q_norm, qnh, qnl, sqn, QLORA, QLORA, NTOK * QLORA);
    kv_post_quant<<<NTOK, 256>>>(kv_norm, freqs);

    wmax<<<NQB / 32, 256>>>(wq_b, swqb, QLORA, NQB);
    wquant<<<dim3(NQB / 32, QLORA / 128), 256>>>(wq_b, swqb, wqbh, wqbl, QLORA, NQB);
    gemm_i8<<<dim3(NQB / 64, NTOK / 128), 256, GEMM_SMEM>>>(
        qnh, qnl, wqbh, wqbl, sqn, swqb, nullptr, NTOK, NQB, QLORA, QLORA, 1);

    wmax<<<NKVB / 32, 256>>>(wkv_b, swkvb, KVLORA, NKVB);
    wquant<<<dim3(NKVB / 32, KVLORA / 128), 256>>>(wkv_b, swkvb, wkvbh, wkvbl, KVLORA, NKVB);
    gemm_i8<<<dim3(NKVB / 64, NTOK / 128), 256, GEMM_SMEM>>>(
        kvnh, kvnl, wkvbh, wkvbl, skvn, swkvb, nullptr, NTOK, NKVB, KVLORA, KVLORA, 2);

    flash_attn<<<BATCH * NHEADS, 256, FLASH_SMEM>>>();
    act_quant<<<NTOK, 256>>>(ao, aoh, aol, sao, DIM);

    wmax<<<DIM / 32, 256>>>(wo, swo, DIM, DIM);
    wquant<<<dim3(DIM / 32, DIM / 128), 256>>>(wo, swo, woh, wol, DIM, DIM);
    gemm_i8<<<dim3(DIM / 64, NTOK / 128, 2), 256, GEMM_SMEM>>>(
        aoh, aol, woh, wol, sao, swo, out2, NTOK, DIM, DIM, DIM / 2, 0);
    add2<<<NTOK * DIM / 4 / 256, 256>>>(out2, out2 + (size_t)NTOK * DIM, out, NTOK * DIM);
}

// round 12
// speedup vs baseline: 1.2942x; 1.2942x over previous
#include <cuda_runtime.h>
#include <cuda_bf16.h>
#include <math.h>
#include <stdint.h>

#define NHEADS 32
#define QKH    192
#define NOPE   128
#define ROPE   64
#define VH     128
#define KVLORA 512
#define DIM    4096
#define QLORA  1536
#define BATCH  8
#define SEQ    128
#define NTOK   1024
#define NKV    576
#define NKVP   640
#define NQB    6144
#define NKVB   8192
#define NC1    2176

typedef __nv_bfloat16 bf16;

// ---------------- scratch ----------------
__device__ float g_qkva[2 * NTOK * NC1];
__device__ float g_out2[2 * NTOK * DIM];

__device__ bf16 g_wc_h   [NC1 * DIM],     g_wc_l   [NC1 * DIM];
__device__ bf16 g_wqbT_h [NQB * QLORA],   g_wqbT_l [NQB * QLORA];
__device__ bf16 g_wkvbT_h[NKVB * KVLORA], g_wkvbT_l[NKVB * KVLORA];
__device__ bf16 g_woT_h  [DIM * DIM],     g_woT_l  [DIM * DIM];

__device__ bf16 g_x_h  [NTOK * DIM],    g_x_l  [NTOK * DIM];
__device__ bf16 g_qn_h [NTOK * QLORA],  g_qn_l [NTOK * QLORA];
__device__ bf16 g_kvn_h[NTOK * KVLORA], g_kvn_l[NTOK * KVLORA];
__device__ bf16 g_ao_h [NTOK * DIM],    g_ao_l [NTOK * DIM];

__device__ bf16 g_qp_h[BATCH * NHEADS * SEQ * QKH], g_qp_l[BATCH * NHEADS * SEQ * QKH];
__device__ bf16 g_kp_h[BATCH * NHEADS * SEQ * QKH], g_kp_l[BATCH * NHEADS * SEQ * QKH];
__device__ bf16 g_vT_h[BATCH * NHEADS * VH * SEQ],  g_vT_l[BATCH * NHEADS * VH * SEQ];

// ---------------- helpers ----------------
__device__ __forceinline__ uint32_t smem_u32(const void* p) {
    uint32_t a;
    asm("{ .reg .u64 t; cvta.to.shared.u64 t, %1; cvt.u32.u64 %0, t; }" : "=r"(a) : "l"(p));
    return a;
}
#define CP_ASYNC(dst, src) asm volatile("cp.async.cg.shared.global [%0], [%1], 16;" :: "r"(dst), "l"(src))
#define CP_COMMIT()        asm volatile("cp.async.commit_group;")
#define CP_WAIT1()         asm volatile("cp.async.wait_group 1;")
#define CP_WAIT0()         asm volatile("cp.async.wait_group 0;")

#define LDM_X4(r0, r1, r2, r3, a) \
    asm volatile("ldmatrix.sync.aligned.m8n8.x4.shared.b16 {%0,%1,%2,%3}, [%4];" \
        : "=r"(r0), "=r"(r1), "=r"(r2), "=r"(r3) : "r"(a))

#define MMA(d, a, b0, b1) \
    asm volatile("mma.sync.aligned.m16n8k16.row.col.f32.bf16.bf16.f32 " \
        "{%0,%1,%2,%3}, {%4,%5,%6,%7}, {%8,%9}, {%0,%1,%2,%3};" \
        : "+f"((d)[0]), "+f"((d)[1]), "+f"((d)[2]), "+f"((d)[3]) \
        : "r"((a)[0]), "r"((a)[1]), "r"((a)[2]), "r"((a)[3]), "r"(b0), "r"(b1))

__device__ __forceinline__ void split_bf16(float v, unsigned short& h, unsigned short& l) {
    bf16 hb = __float2bfloat16(v);
    h = __bfloat16_as_ushort(hb);
    l = __bfloat16_as_ushort(__float2bfloat16(v - __bfloat162float(hb)));
}

// ---------------- split-bf16 GEMM: 256 thr, 8 warps 4x2, warp tile 32x64 --------
#define SROW    40
#define PART_B  (128 * SROW * 2)
#define STAGE_B (4 * PART_B)

__global__ void __launch_bounds__(256, 2)
gemm_mma(const bf16* __restrict__ Ah, const bf16* __restrict__ Al,
         const bf16* __restrict__ Bh, const bf16* __restrict__ Bl,
         float* __restrict__ C, int M, int N, int K, int ksl, int mode) {
    extern __shared__ char smem[];
    const uint32_t sb = smem_u32(smem);
    const int tid = threadIdx.x, lane = tid & 31, wid = tid >> 5;
    const int m0 = blockIdx.y * 128, n0 = blockIdx.x * 128;
    const int wm = wid & 3, wn = wid >> 2;
    const int ks = blockIdx.z * ksl;

    const bf16* gp[4] = { Ah + (size_t)m0 * K + ks, Al + (size_t)m0 * K + ks,
                          Bh + (size_t)n0 * K + ks, Bl + (size_t)n0 * K + ks };
    const int r0c = tid >> 2, c0c = (tid & 3) * 8;

    float acc[2][8][4];
    #pragma unroll
    for (int i = 0; i < 2; i++)
        #pragma unroll
        for (int j = 0; j < 8; j++)
            #pragma unroll
            for (int k = 0; k < 4; k++) acc[i][j][k] = 0.f;

    const int kt = ksl >> 5;
    #pragma unroll
    for (int s = 0; s < 2; s++) {
        const int k0 = s * 32;
        const uint32_t st = sb + s * STAGE_B;
        #pragma unroll
        for (int p = 0; p < 4; p++) {
            CP_ASYNC(st + p * PART_B + r0c * 80 + c0c * 2, gp[p] + (size_t)r0c * K + k0 + c0c);
            CP_ASYNC(st + p * PART_B + (r0c + 64) * 80 + c0c * 2, gp[p] + (size_t)(r0c + 64) * K + k0 + c0c);
        }
        CP_COMMIT();
    }

    const int rA = lane & 15, gA = lane >> 4;
    const uint32_t aoff = (uint32_t)(((wm * 32 + rA) * SROW + gA * 8) * 2);
    const int rB = lane & 7, gB = lane >> 3;
    const uint32_t boff = (uint32_t)(((wn * 64 + (gB & 1) * 8 + rB) * SROW + (gB >> 1) * 8) * 2);

    for (int it = 0; it < kt; it++) {
        CP_WAIT1();
        __syncthreads();
        const uint32_t st = sb + (it & 1) * STAGE_B;
        const uint32_t sAh = st, sAl = st + PART_B, sBh = st + 2 * PART_B, sBl = st + 3 * PART_B;
        #pragma unroll
        for (int k2 = 0; k2 < 2; k2++) {
            const uint32_t ko = k2 * 32;
            uint32_t ah[2][4], al[2][4];
            #pragma unroll
            for (int mt = 0; mt < 2; mt++) {
                LDM_X4(ah[mt][0], ah[mt][1], ah[mt][2], ah[mt][3], sAh + aoff + mt * (16 * SROW * 2) + ko);
                LDM_X4(al[mt][0], al[mt][1], al[mt][2], al[mt][3], sAl + aoff + mt * (16 * SROW * 2) + ko);
            }
            #pragma unroll
            for (int ng = 0; ng < 4; ng++) {
                uint32_t bh[4], bl[4];
                LDM_X4(bh[0], bh[1], bh[2], bh[3], sBh + boff + ng * (16 * SROW * 2) + ko);
                LDM_X4(bl[0], bl[1], bl[2], bl[3], sBl + boff + ng * (16 * SROW * 2) + ko);
                // product-major: RAW distance 4 on each accumulator, no extra regs
                #pragma unroll
                for (int mt = 0; mt < 2; mt++)
                    #pragma unroll
                    for (int h = 0; h < 2; h++)
                        MMA(acc[mt][ng * 2 + h], ah[mt], bh[h], bh[2 + h]);
                #pragma unroll
                for (int mt = 0; mt < 2; mt++)
                    #pragma unroll
                    for (int h = 0; h < 2; h++)
                        MMA(acc[mt][ng * 2 + h], ah[mt], bl[h], bl[2 + h]);
                #pragma unroll
                for (int mt = 0; mt < 2; mt++)
                    #pragma unroll
                    for (int h = 0; h < 2; h++)
                        MMA(acc[mt][ng * 2 + h], al[mt], bh[h], bh[2 + h]);
            }
        }
        __syncthreads();
        const int kn = it + 2;
        if (kn < kt) {
            const int k0 = kn * 32;
            const uint32_t s2 = sb + (it & 1) * STAGE_B;
            #pragma unroll
            for (int p = 0; p < 4; p++) {
                CP_ASYNC(s2 + p * PART_B + r0c * 80 + c0c * 2, gp[p] + (size_t)r0c * K + k0 + c0c);
                CP_ASYNC(s2 + p * PART_B + (r0c + 64) * 80 + c0c * 2, gp[p] + (size_t)(r0c + 64) * K + k0 + c0c);
            }
        }
        CP_COMMIT();
    }

    if (mode == 0) {
        float* Cz = C + (size_t)blockIdx.z * M * N;
        #pragma unroll
        for (int mt = 0; mt < 2; mt++) {
            const int row = m0 + wm * 32 + mt * 16 + (lane >> 2);
            #pragma unroll
            for (int nt = 0; nt < 8; nt++) {
                const int col = n0 + wn * 64 + nt * 8 + (lane & 3) * 2;
                if (col < N) {
                    *(float2*)&Cz[(size_t)row * N + col] = make_float2(acc[mt][nt][0], acc[mt][nt][1]);
                    *(float2*)&Cz[(size_t)(row + 8) * N + col] = make_float2(acc[mt][nt][2], acc[mt][nt][3]);
                }
            }
        }
    } else if (mode == 1) {
        #pragma unroll
        for (int mt = 0; mt < 2; mt++) {
            const int row = m0 + wm * 32 + mt * 16 + (lane >> 2);
            const int b = row >> 7, t = row & 127;
            #pragma unroll
            for (int nt = 0; nt < 8; nt++) {
                const int c = n0 + wn * 64 + nt * 8 + (lane & 3) * 2;
                const int h = c / 192, d = c - h * 192;
                const size_t base = ((size_t)((b * 32 + h) * 128 + t)) * 192 + d;
                unsigned short h0, l0, h1, l1;
                split_bf16(acc[mt][nt][0], h0, l0); split_bf16(acc[mt][nt][1], h1, l1);
                *(uint32_t*)((unsigned short*)g_qp_h + base) = h0 | ((uint32_t)h1 << 16);
                *(uint32_t*)((unsigned short*)g_qp_l + base) = l0 | ((uint32_t)l1 << 16);
                split_bf16(acc[mt][nt][2], h0, l0); split_bf16(acc[mt][nt][3], h1, l1);
                *(uint32_t*)((unsigned short*)g_qp_h + base + 8 * 192) = h0 | ((uint32_t)h1 << 16);
                *(uint32_t*)((unsigned short*)g_qp_l + base + 8 * 192) = l0 | ((uint32_t)l1 << 16);
            }
        }
    } else {
        const int h = n0 >> 8;
        const int b = m0 >> 7;
        if ((n0 & 255) == 0) {
            #pragma unroll
            for (int mt = 0; mt < 2; mt++) {
                const int t = (wm * 32 + mt * 16 + (lane >> 2)) & 127;
                #pragma unroll
                for (int nt = 0; nt < 8; nt++) {
                    const int d = wn * 64 + nt * 8 + (lane & 3) * 2;
                    const size_t base = ((size_t)((b * 32 + h) * 128 + t)) * 192 + d;
                    unsigned short h0, l0, h1, l1;
                    split_bf16(acc[mt][nt][0], h0, l0); split_bf16(acc[mt][nt][1], h1, l1);
                    *(uint32_t*)((unsigned short*)g_kp_h + base) = h0 | ((uint32_t)h1 << 16);
                    *(uint32_t*)((unsigned short*)g_kp_l + base) = l0 | ((uint32_t)l1 << 16);
                    split_bf16(acc[mt][nt][2], h0, l0); split_bf16(acc[mt][nt][3], h1, l1);
                    *(uint32_t*)((unsigned short*)g_kp_h + base + 8 * 192) = h0 | ((uint32_t)h1 << 16);
                    *(uint32_t*)((unsigned short*)g_kp_l + base + 8 * 192) = l0 | ((uint32_t)l1 << 16);
                }
            }
        } else {
            __syncthreads();
            float* T = (float*)smem;  // [128 dv][132]
            #pragma unroll
            for (int mt = 0; mt < 2; mt++) {
                const int tl = wm * 32 + mt * 16 + (lane >> 2);
                #pragma unroll
                for (int nt = 0; nt < 8; nt++) {
                    const int dv = wn * 64 + nt * 8 + (lane & 3) * 2;
                    T[(dv) * 132 + tl]         = acc[mt][nt][0];
                    T[(dv + 1) * 132 + tl]     = acc[mt][nt][1];
                    T[(dv) * 132 + tl + 8]     = acc[mt][nt][2];
                    T[(dv + 1) * 132 + tl + 8] = acc[mt][nt][3];
                }
            }
            __syncthreads();
            const size_t vb = ((size_t)((b * 32 + h) * 128)) * 128;
            for (int i = tid; i < 4096; i += 256) {
                const int dv = i >> 5, tq = (i & 31) * 4;
                const float* r = T + dv * 132 + tq;
                unsigned short h0, l0, h1, l1, h2, l2, h3, l3;
                split_bf16(r[0], h0, l0); split_bf16(r[1], h1, l1);
                split_bf16(r[2], h2, l2); split_bf16(r[3], h3, l3);
                const size_t o = vb + (size_t)dv * 128 + tq;
                *(uint2*)((unsigned short*)g_vT_h + o) = make_uint2(h0 | ((uint32_t)h1 << 16), h2 | ((uint32_t)h3 << 16));
                *(uint2*)((unsigned short*)g_vT_l + o) = make_uint2(l0 | ((uint32_t)l1 << 16), l2 | ((uint32_t)l3 << 16));
            }
        }
    }
}

// ---------------- small kernels ----------------
__global__ void __launch_bounds__(256) add2(const float* __restrict__ a,
                                            const float* __restrict__ b,
                                            float* __restrict__ o, int n) {
    const int i = (blockIdx.x * 256 + threadIdx.x) * 4;
    if (i >= n) return;
    float4 va = *(const float4*)(a + i);
    float4 vb = *(const float4*)(b + i);
    *(float4*)(o + i) = make_float4(va.x + vb.x, va.y + vb.y, va.z + vb.z, va.w + vb.w);
}

__global__ void __launch_bounds__(256) act_pack(const float* __restrict__ in,
                                                bf16* __restrict__ hi, bf16* __restrict__ lo, int n) {
    const int i = (blockIdx.x * 256 + threadIdx.x) * 4;
    if (i >= n) return;
    float4 v = *(const float4*)(in + i);
    unsigned short h[4], l[4];
    split_bf16(v.x, h[0], l[0]); split_bf16(v.y, h[1], l[1]);
    split_bf16(v.z, h[2], l[2]); split_bf16(v.w, h[3], l[3]);
    *(uint2*)((unsigned short*)hi + i) = make_uint2(h[0] | ((uint32_t)h[1] << 16), h[2] | ((uint32_t)h[3] << 16));
    *(uint2*)((unsigned short*)lo + i) = make_uint2(l[0] | ((uint32_t)l[1] << 16), l[2] | ((uint32_t)l[3] << 16));
}

__global__ void __launch_bounds__(256) wt_pack2(const float* __restrict__ W,
                                                bf16* __restrict__ oh, bf16* __restrict__ ol,
                                                int K, int N) {
    __shared__ float tile[128][33];
    const int n0 = blockIdx.x * 32, k0 = blockIdx.y * 128;
    const int tid = threadIdx.x;
    const int lr = tid >> 3, lc = (tid & 7) * 4;
    if (n0 < N) {
        #pragma unroll
        for (int j = 0; j < 4; j++) {
            const int k = k0 + lr + j * 32;
            float4 v = *(const float4*)(W + (size_t)k * N + n0 + lc);
            tile[lr + j * 32][lc] = v.x; tile[lr + j * 32][lc + 1] = v.y;
            tile[lr + j * 32][lc + 2] = v.z; tile[lr + j * 32][lc + 3] = v.w;
        }
    } else {
        #pragma unroll
        for (int j = 0; j < 4; j++) {
            tile[lr + j * 32][lc] = 0.f; tile[lr + j * 32][lc + 1] = 0.f;
            tile[lr + j * 32][lc + 2] = 0.f; tile[lr + j * 32][lc + 3] = 0.f;
        }
    }
    __syncthreads();
    const int nl = tid >> 3, kk = (tid & 7) * 16;
    const size_t ob = (size_t)(n0 + nl) * K + k0 + kk;
    #pragma unroll
    for (int i = 0; i < 8; i++) {
        unsigned short h0, l0, h1, l1;
        split_bf16(tile[kk + 2 * i][nl], h0, l0);
        split_bf16(tile[kk + 2 * i + 1][nl], h1, l1);
        *(uint32_t*)((unsigned short*)oh + ob + 2 * i) = h0 | ((uint32_t)h1 << 16);
        *(uint32_t*)((unsigned short*)ol + ob + 2 * i) = l0 | ((uint32_t)l1 << 16);
    }
}

__global__ void __launch_bounds__(256) rmsnorm_pack(const float* __restrict__ in,
                                                    const float* __restrict__ w,
                                                    bf16* __restrict__ hi, bf16* __restrict__ lo,
                                                    int ncols, int ld, int poff) {
    const int row = blockIdx.x;
    const float* p0 = in + (size_t)row * ld;
    const float* p1 = p0 + (size_t)poff;
    float ss = 0.f;
    for (int i = threadIdx.x; i < ncols; i += 256) { float v = p0[i] + p1[i]; ss += v * v; }
    __shared__ float red[256];
    red[threadIdx.x] = ss; __syncthreads();
    for (int off = 128; off > 0; off >>= 1) {
        if (threadIdx.x < off) red[threadIdx.x] += red[threadIdx.x + off];
        __syncthreads();
    }
    const float scale = rsqrtf(red[0] / (float)ncols + 1e-6f);
    for (int i = threadIdx.x; i < ncols; i += 256) {
        unsigned short h, l;
        split_bf16((p0[i] + p1[i]) * scale * w[i], h, l);
        ((unsigned short*)hi)[(size_t)row * ncols + i] = h;
        ((unsigned short*)lo)[(size_t)row * ncols + i] = l;
    }
}

__global__ void __launch_bounds__(256) kv_post_pack(const float* __restrict__ w,
                                                    const float* __restrict__ freqs) {
    const int tg = blockIdx.x;
    const int b = tg >> 7, s = tg & 127;
    const float* p0 = g_qkva + (size_t)tg * NC1 + QLORA;
    const float* p1 = p0 + (size_t)NTOK * NC1;
    float ss = 0.f;
    for (int i = threadIdx.x; i < KVLORA; i += 256) { float v = p0[i] + p1[i]; ss += v * v; }
    __shared__ float red[256];
    red[threadIdx.x] = ss; __syncthreads();
    for (int off = 128; off > 0; off >>= 1) {
        if (threadIdx.x < off) red[threadIdx.x] += red[threadIdx.x + off];
        __syncthreads();
    }
    const float scale = rsqrtf(red[0] / (float)KVLORA + 1e-6f);
    for (int i = threadIdx.x; i < KVLORA; i += 256) {
        unsigned short h, l;
        split_bf16((p0[i] + p1[i]) * scale * w[i], h, l);
        ((unsigned short*)g_kvn_h)[(size_t)tg * KVLORA + i] = h;
        ((unsigned short*)g_kvn_l)[(size_t)tg * KVLORA + i] = l;
    }
    if (threadIdx.x < ROPE) {
        const int d = threadIdx.x;
        unsigned short h, l;
        split_bf16((p0[KVLORA + d] + p1[KVLORA + d]) * freqs[s * (ROPE / 2) + (d >> 1)], h, l);
        #pragma unroll 4
        for (int hh = 0; hh < NHEADS; hh++) {
            const size_t a = ((size_t)((b * 32 + hh) * 128 + s)) * 192 + 128 + d;
            ((unsigned short*)g_kp_h)[a] = h;
            ((unsigned short*)g_kp_l)[a] = l;
        }
    }
}

// ---------------- fused flash attention per (b,h) ----------------
#define VBASE  81920
#define PLBASE 34816
#define REDOFF 122880
#define PSTR   136
#define FLASH_SMEM 124928

__global__ void __launch_bounds__(256, 1) flash_attn() {
    extern __shared__ char smem[];
    const uint32_t sb = smem_u32(smem);
    const int tid = threadIdx.x, lane = tid & 31, wid = tid >> 5;
    const int wm = wid & 3, wn = wid >> 2;
    const int bh = blockIdx.x, b = bh >> 5, h = bh & 31;

    const bf16* gqh = g_qp_h + (size_t)bh * SEQ * QKH;
    const bf16* gql = g_qp_l + (size_t)bh * SEQ * QKH;
    const bf16* gkh = g_kp_h + (size_t)bh * SEQ * QKH;
    const bf16* gkl = g_kp_l + (size_t)bh * SEQ * QKH;
    const bf16* gvh = g_vT_h + (size_t)bh * VH * SEQ;
    const bf16* gvl = g_vT_l + (size_t)bh * VH * SEQ;
    const bf16* gp[4] = { gqh, gql, gkh, gkl };

    const int r0c = tid >> 2, c0c = (tid & 3) * 8;

    #pragma unroll
    for (int s = 0; s < 2; s++) {
        const int k0 = s * 32;
        const uint32_t st = sb + s * STAGE_B;
        #pragma unroll
        for (int p = 0; p < 4; p++) {
            CP_ASYNC(st + p * PART_B + r0c * 80 + c0c * 2, gp[p] + (size_t)r0c * QKH + k0 + c0c);
            CP_ASYNC(st + p * PART_B + (r0c + 64) * 80 + c0c * 2, gp[p] + (size_t)(r0c + 64) * QKH + k0 + c0c);
        }
        const uint32_t vst = sb + VBASE + s * 20480;
        CP_ASYNC(vst + r0c * 80 + c0c * 2, gvh + (size_t)r0c * SEQ + k0 + c0c);
        CP_ASYNC(vst + (r0c + 64) * 80 + c0c * 2, gvh + (size_t)(r0c + 64) * SEQ + k0 + c0c);
        CP_ASYNC(vst + 10240 + r0c * 80 + c0c * 2, gvl + (size_t)r0c * SEQ + k0 + c0c);
        CP_ASYNC(vst + 10240 + (r0c + 64) * 80 + c0c * 2, gvl + (size_t)(r0c + 64) * SEQ + k0 + c0c);
        CP_COMMIT();
    }

    const int rA = lane & 15, gA = lane >> 4;
    const uint32_t aoff = (uint32_t)(((wm * 32 + rA) * SROW + gA * 8) * 2);
    const int rB = lane & 7, gB = lane >> 3;
    const uint32_t boff = (uint32_t)(((wn * 64 + (gB & 1) * 8 + rB) * SROW + (gB >> 1) * 8) * 2);

    float acc[2][8][4];
    #pragma unroll
    for (int i = 0; i < 2; i++)
        #pragma unroll
        for (int j = 0; j < 8; j++)
            #pragma unroll
            for (int k = 0; k < 4; k++) acc[i][j][k] = 0.f;

    for (int it = 0; it < 6; it++) {
        CP_WAIT1();
        __syncthreads();
        const uint32_t st = sb + (it & 1) * STAGE_B;
        const uint32_t sAh = st, sAl = st + PART_B, sBh = st + 2 * PART_B, sBl = st + 3 * PART_B;
        #pragma unroll
        for (int k2 = 0; k2 < 2; k2++) {
            const uint32_t ko = k2 * 32;
            uint32_t ah[2][4], al[2][4];
            #pragma unroll
            for (int mt = 0; mt < 2; mt++) {
                LDM_X4(ah[mt][0], ah[mt][1], ah[mt][2], ah[mt][3], sAh + aoff + mt * (16 * SROW * 2) + ko);
                LDM_X4(al[mt][0], al[mt][1], al[mt][2], al[mt][3], sAl + aoff + mt * (16 * SROW * 2) + ko);
            }
            #pragma unroll
            for (int ng = 0; ng < 4; ng++) {
                uint32_t bh2[4], bl2[4];
                LDM_X4(bh2[0], bh2[1], bh2[2], bh2[3], sBh + boff + ng * (16 * SROW * 2) + ko);
                LDM_X4(bl2[0], bl2[1], bl2[2], bl2[3], sBl + boff + ng * (16 * SROW * 2) + ko);
                #pragma unroll
                for (int mt = 0; mt < 2; mt++)
                    #pragma unroll
                    for (int hh = 0; hh < 2; hh++)
                        MMA(acc[mt][ng * 2 + hh], ah[mt], bh2[hh], bh2[2 + hh]);
                #pragma unroll
                for (int mt = 0; mt < 2; mt++)
                    #pragma unroll
                    for (int hh = 0; hh < 2; hh++)
                        MMA(acc[mt][ng * 2 + hh], ah[mt], bl2[hh], bl2[2 + hh]);
                #pragma unroll
                for (int mt = 0; mt < 2; mt++)
                    #pragma unroll
                    for (int hh = 0; hh < 2; hh++)
                        MMA(acc[mt][ng * 2 + hh], al[mt], bh2[hh], bh2[2 + hh]);
            }
        }
        __syncthreads();
        const int kn = it + 2;
        if (kn < 6) {
            const int k0 = kn * 32;
            const uint32_t s2 = sb + (it & 1) * STAGE_B;
            #pragma unroll
            for (int p = 0; p < 4; p++) {
                CP_ASYNC(s2 + p * PART_B + r0c * 80 + c0c * 2, gp[p] + (size_t)r0c * QKH + k0 + c0c);
                CP_ASYNC(s2 + p * PART_B + (r0c + 64) * 80 + c0c * 2, gp[p] + (size_t)(r0c + 64) * QKH + k0 + c0c);
            }
        }
        CP_COMMIT();
    }
    CP_WAIT0();
    __syncthreads();

    float* RMAX = (float*)(smem + REDOFF);
    float* RSUM = (float*)(smem + REDOFF + 1024);
    const float scl = 0.07216878364870323f;
    const int rbase = wm * 32 + (lane >> 2);
    const int cbase = wn * 64 + (lane & 3) * 2;

    #pragma unroll
    for (int mt = 0; mt < 2; mt++)
        #pragma unroll
        for (int nt = 0; nt < 8; nt++)
            #pragma unroll
            for (int k = 0; k < 4; k++) {
                const int r = rbase + mt * 16 + (k >> 1) * 8;
                const int c = cbase + nt * 8 + (k & 1);
                float v = acc[mt][nt][k] * scl;
                acc[mt][nt][k] = (c > r) ? -INFINITY : v;
            }

    #pragma unroll
    for (int mt = 0; mt < 2; mt++)
        #pragma unroll
        for (int hf = 0; hf < 2; hf++) {
            float m = -INFINITY;
            #pragma unroll
            for (int nt = 0; nt < 8; nt++)
                m = fmaxf(m, fmaxf(acc[mt][nt][hf * 2], acc[mt][nt][hf * 2 + 1]));
            m = fmaxf(m, __shfl_xor_sync(0xffffffffu, m, 1));
            m = fmaxf(m, __shfl_xor_sync(0xffffffffu, m, 2));
            if ((lane & 3) == 0) RMAX[wn * 128 + rbase + mt * 16 + hf * 8] = m;
        }
    __syncthreads();
    #pragma unroll
    for (int mt = 0; mt < 2; mt++)
        #pragma unroll
        for (int hf = 0; hf < 2; hf++) {
            const int r = rbase + mt * 16 + hf * 8;
            const float m = fmaxf(RMAX[r], RMAX[128 + r]);
            float s = 0.f;
            #pragma unroll
            for (int nt = 0; nt < 8; nt++) {
                float p0 = expf(acc[mt][nt][hf * 2] - m);
                float p1 = expf(acc[mt][nt][hf * 2 + 1] - m);
                acc[mt][nt][hf * 2] = p0; acc[mt][nt][hf * 2 + 1] = p1;
                s += p0 + p1;
            }
            s += __shfl_xor_sync(0xffffffffu, s, 1);
            s += __shfl_xor_sync(0xffffffffu, s, 2);
            if ((lane & 3) == 0) RSUM[wn * 128 + r] = s;
        }
    #pragma unroll
    for (int mt = 0; mt < 2; mt++)
        #pragma unroll
        for (int nt = 0; nt < 8; nt++)
            #pragma unroll
            for (int hf = 0; hf < 2; hf++) {
                const int r = rbase + mt * 16 + hf * 8;
                const int c = cbase + nt * 8;
                unsigned short h0, l0, h1, l1;
                split_bf16(acc[mt][nt][hf * 2], h0, l0);
                split_bf16(acc[mt][nt][hf * 2 + 1], h1, l1);
                *(uint32_t*)(smem + (r * PSTR + c) * 2) = h0 | ((uint32_t)h1 << 16);
                *(uint32_t*)(smem + PLBASE + (r * PSTR + c) * 2) = l0 | ((uint32_t)l1 << 16);
            }
    __syncthreads();

    const uint32_t aoffP = (uint32_t)(((wm * 32 + rA) * PSTR + gA * 8) * 2);
    float o[2][8][4];
    #pragma unroll
    for (int i = 0; i < 2; i++)
        #pragma unroll
        for (int j = 0; j < 8; j++)
            #pragma unroll
            for (int k = 0; k < 4; k++) o[i][j][k] = 0.f;

    for (int it = 0; it < 4; it++) {
        CP_WAIT1();
        __syncthreads();
        const uint32_t vst = sb + VBASE + (it & 1) * 20480;
        #pragma unroll
        for (int k2 = 0; k2 < 2; k2++) {
            const uint32_t kP = (it * 32 + k2 * 16) * 2;
            const uint32_t kV = k2 * 32;
            uint32_t ph[2][4], pl[2][4];
            #pragma unroll
            for (int mt = 0; mt < 2; mt++) {
                LDM_X4(ph[mt][0], ph[mt][1], ph[mt][2], ph[mt][3], sb + aoffP + mt * (16 * PSTR * 2) + kP);
                LDM_X4(pl[mt][0], pl[mt][1], pl[mt][2], pl[mt][3], sb + PLBASE + aoffP + mt * (16 * PSTR * 2) + kP);
            }
            #pragma unroll
            for (int ng = 0; ng < 4; ng++) {
                uint32_t vh[4], vl[4];
                LDM_X4(vh[0], vh[1], vh[2], vh[3], vst + boff + ng * (16 * SROW * 2) + kV);
                LDM_X4(vl[0], vl[1], vl[2], vl[3], vst + 10240 + boff + ng * (16 * SROW * 2) + kV);
                #pragma unroll
                for (int mt = 0; mt < 2; mt++)
                    #pragma unroll
                    for (int hh = 0; hh < 2; hh++)
                        MMA(o[mt][ng * 2 + hh], ph[mt], vh[hh], vh[2 + hh]);
                #pragma unroll
                for (int mt = 0; mt < 2; mt++)
                    #pragma unroll
                    for (int hh = 0; hh < 2; hh++)
                        MMA(o[mt][ng * 2 + hh], ph[mt], vl[hh], vl[2 + hh]);
                #pragma unroll
                for (int mt = 0; mt < 2; mt++)
                    #pragma unroll
                    for (int hh = 0; hh < 2; hh++)
                        MMA(o[mt][ng * 2 + hh], pl[mt], vh[hh], vh[2 + hh]);
            }
        }
        __syncthreads();
        const int kn = it + 2;
        if (kn < 4) {
            const int k0 = kn * 32;
            const uint32_t v2 = sb + VBASE + (it & 1) * 20480;
            CP_ASYNC(v2 + r0c * 80 + c0c * 2, gvh + (size_t)r0c * SEQ + k0 + c0c);
            CP_ASYNC(v2 + (r0c + 64) * 80 + c0c * 2, gvh + (size_t)(r0c + 64) * SEQ + k0 + c0c);
            CP_ASYNC(v2 + 10240 + r0c * 80 + c0c * 2, gvl + (size_t)r0c * SEQ + k0 + c0c);
            CP_ASYNC(v2 + 10240 + (r0c + 64) * 80 + c0c * 2, gvl + (size_t)(r0c + 64) * SEQ + k0 + c0c);
        }
        CP_COMMIT();
    }

    #pragma unroll
    for (int mt = 0; mt < 2; mt++) {
        float inv[2];
        #pragma unroll
        for (int hf = 0; hf < 2; hf++) {
            const int r = rbase + mt * 16 + hf * 8;
            inv[hf] = 1.f / (RSUM[r] + RSUM[128 + r]);
        }
        #pragma unroll
        for (int nt = 0; nt < 8; nt++) {
            const int c = cbase + nt * 8;
            #pragma unroll
            for (int hf = 0; hf < 2; hf++) {
                const int r = rbase + mt * 16 + hf * 8;
                const size_t off = (size_t)(b * SEQ + r) * DIM + h * VH + c;
                unsigned short h0, l0, h1, l1;
                split_bf16(o[mt][nt][hf * 2] * inv[hf], h0, l0);
                split_bf16(o[mt][nt][hf * 2 + 1] * inv[hf], h1, l1);
                *(uint32_t*)((unsigned short*)g_ao_h + off) = h0 | ((uint32_t)h1 << 16);
                *(uint32_t*)((unsigned short*)g_ao_l + off) = l0 | ((uint32_t)l1 << 16);
            }
        }
    }
}

// ---------------- launch ----------------
extern "C" void kernel_launch(void* const* d_in, const int* in_sizes, int n_in,
                              void* d_out, int out_size) {
    const float* x       = (const float*)d_in[0];
    const float* freqs   = (const float*)d_in[1];
    const float* wq_a    = (const float*)d_in[2];
    const float* q_norm  = (const float*)d_in[3];
    const float* wq_b    = (const float*)d_in[4];
    const float* wkv_a   = (const float*)d_in[5];
    const float* kv_norm = (const float*)d_in[6];
    const float* wkv_b   = (const float*)d_in[7];
    const float* wo      = (const float*)d_in[8];
    float* out = (float*)d_out;

    const int GEMM_SMEM = 2 * STAGE_B;
    cudaFuncSetAttribute(gemm_mma, cudaFuncAttributeMaxDynamicSharedMemorySize, GEMM_SMEM);
    cudaFuncSetAttribute(flash_attn, cudaFuncAttributeMaxDynamicSharedMemorySize, FLASH_SMEM);

    float *qkva, *out2;
    bf16 *xh, *xl, *qnh, *qnl, *kvnh, *kvnl, *aoh, *aol;
    bf16 *wch, *wcl, *wqbh, *wqbl, *wkvbh, *wkvbl, *woh, *wol;
    cudaGetSymbolAddress((void**)&qkva, g_qkva);
    cudaGetSymbolAddress((void**)&out2, g_out2);
    cudaGetSymbolAddress((void**)&xh,   g_x_h);   cudaGetSymbolAddress((void**)&xl,   g_x_l);
    cudaGetSymbolAddress((void**)&qnh,  g_qn_h);  cudaGetSymbolAddress((void**)&qnl,  g_qn_l);
    cudaGetSymbolAddress((void**)&kvnh, g_kvn_h); cudaGetSymbolAddress((void**)&kvnl, g_kvn_l);
    cudaGetSymbolAddress((void**)&aoh,  g_ao_h);  cudaGetSymbolAddress((void**)&aol,  g_ao_l);
    cudaGetSymbolAddress((void**)&wch,  g_wc_h);  cudaGetSymbolAddress((void**)&wcl,  g_wc_l);
    cudaGetSymbolAddress((void**)&wqbh,  g_wqbT_h);  cudaGetSymbolAddress((void**)&wqbl,  g_wqbT_l);
    cudaGetSymbolAddress((void**)&wkvbh, g_wkvbT_h); cudaGetSymbolAddress((void**)&wkvbl, g_wkvbT_l);
    cudaGetSymbolAddress((void**)&woh,   g_woT_h);   cudaGetSymbolAddress((void**)&wol,   g_woT_l);

    // #1-3 packs, #4 = gemm1 split-K2 (profiled slot)
    act_pack<<<NTOK * DIM / 4 / 256, 256>>>(x, xh, xl, NTOK * DIM);
    wt_pack2<<<dim3(QLORA / 32, DIM / 128), 256>>>(wq_a, wch, wcl, DIM, QLORA);
    wt_pack2<<<dim3(NKVP / 32, DIM / 128), 256>>>(wkv_a, wch + (size_t)QLORA * DIM, wcl + (size_t)QLORA * DIM, DIM, NKV);

    gemm_mma<<<dim3(NC1 / 128, NTOK / 128, 2), 256, GEMM_SMEM>>>(xh, xl, wch, wcl, qkva, NTOK, NC1, DIM, DIM / 2, 0);

    rmsnorm_pack<<<NTOK, 256>>>(qkva, q_norm, qnh, qnl, QLORA, NC1, NTOK * NC1);
    kv_post_pack<<<NTOK, 256>>>(kv_norm, freqs);
    wt_pack2<<<dim3(NQB / 32, QLORA / 128), 256>>>(wq_b, wqbh, wqbl, QLORA, NQB);
    wt_pack2<<<dim3(NKVB / 32, KVLORA / 128), 256>>>(wkv_b, wkvbh, wkvbl, KVLORA, NKVB);

    gemm_mma<<<dim3(NQB / 128, NTOK / 128), 256, GEMM_SMEM>>>(qnh, qnl, wqbh, wqbl, nullptr, NTOK, NQB, QLORA, QLORA, 1);
    gemm_mma<<<dim3(NKVB / 128, NTOK / 128), 256, GEMM_SMEM>>>(kvnh, kvnl, wkvbh, wkvbl, nullptr, NTOK, NKVB, KVLORA, KVLORA, 2);

    flash_attn<<<BATCH * NHEADS, 256, FLASH_SMEM>>>();

    wt_pack2<<<dim3(DIM / 32, DIM / 128), 256>>>(wo, woh, wol, DIM, DIM);
    gemm_mma<<<dim3(DIM / 128, NTOK / 128, 2), 256, GEMM_SMEM>>>(aoh, aol, woh, wol, out2, NTOK, DIM, DIM, DIM / 2, 0);
    add2<<<NTOK * DIM / 4 / 256, 256>>>(out2, out2 + (size_t)NTOK * DIM, out, NTOK * DIM);
}

// round 13
// speedup vs baseline: 1.9939x; 1.5407x over previous
#include <cuda_runtime.h>
#include <cuda_bf16.h>
#include <math.h>
#include <stdint.h>

#define NHEADS 32
#define QKH    192
#define NOPE   128
#define ROPE   64
#define VH     128
#define KVLORA 512
#define DIM    4096
#define QLORA  1536
#define BATCH  8
#define SEQ    128
#define NTOK   1024
#define NKV    576
#define NKVP   640
#define NQB    6144
#define NKVB   8192
#define NC1    2176

typedef __nv_bfloat16 bf16;

// ---------------- scratch ----------------
__device__ float g_qkva[2 * NTOK * NC1];      // split-K partials
__device__ float g_out2[2 * NTOK * DIM];      // wo split-K partials

__device__ bf16 g_wc_h   [NC1 * DIM],     g_wc_l   [NC1 * DIM];
__device__ bf16 g_wqbT_h [NQB * QLORA],   g_wqbT_l [NQB * QLORA];
__device__ bf16 g_wkvbT_h[NKVB * KVLORA], g_wkvbT_l[NKVB * KVLORA];
__device__ bf16 g_woT_h  [DIM * DIM],     g_woT_l  [DIM * DIM];

__device__ bf16 g_x_h  [NTOK * DIM],    g_x_l  [NTOK * DIM];
__device__ bf16 g_qn_h [NTOK * QLORA],  g_qn_l [NTOK * QLORA];
__device__ bf16 g_kvn_h[NTOK * KVLORA], g_kvn_l[NTOK * KVLORA];
__device__ bf16 g_ao_h [NTOK * DIM],    g_ao_l [NTOK * DIM];

__device__ bf16 g_qp_h[BATCH * NHEADS * SEQ * QKH], g_qp_l[BATCH * NHEADS * SEQ * QKH];
__device__ bf16 g_kp_h[BATCH * NHEADS * SEQ * QKH], g_kp_l[BATCH * NHEADS * SEQ * QKH];
__device__ bf16 g_vT_h[BATCH * NHEADS * VH * SEQ],  g_vT_l[BATCH * NHEADS * VH * SEQ];

// ---------------- helpers ----------------
__device__ __forceinline__ uint32_t smem_u32(const void* p) {
    uint32_t a;
    asm("{ .reg .u64 t; cvta.to.shared.u64 t, %1; cvt.u32.u64 %0, t; }" : "=r"(a) : "l"(p));
    return a;
}
#define CP_ASYNC(dst, src) asm volatile("cp.async.cg.shared.global [%0], [%1], 16;" :: "r"(dst), "l"(src))
#define CP_COMMIT()        asm volatile("cp.async.commit_group;")
#define CP_WAIT1()         asm volatile("cp.async.wait_group 1;")
#define CP_WAIT0()         asm volatile("cp.async.wait_group 0;")

#define LDM_X4(r0, r1, r2, r3, a) \
    asm volatile("ldmatrix.sync.aligned.m8n8.x4.shared.b16 {%0,%1,%2,%3}, [%4];" \
        : "=r"(r0), "=r"(r1), "=r"(r2), "=r"(r3) : "r"(a))

#define MMA(d, a, b0, b1) \
    asm volatile("mma.sync.aligned.m16n8k16.row.col.f32.bf16.bf16.f32 " \
        "{%0,%1,%2,%3}, {%4,%5,%6,%7}, {%8,%9}, {%0,%1,%2,%3};" \
        : "+f"((d)[0]), "+f"((d)[1]), "+f"((d)[2]), "+f"((d)[3]) \
        : "r"((a)[0]), "r"((a)[1]), "r"((a)[2]), "r"((a)[3]), "r"(b0), "r"(b1))

__device__ __forceinline__ void split_bf16(float v, unsigned short& h, unsigned short& l) {
    bf16 hb = __float2bfloat16(v);
    h = __bfloat16_as_ushort(hb);
    l = __bfloat16_as_ushort(__float2bfloat16(v - __bfloat162float(hb)));
}

// ---------------- split-bf16 GEMM: 256 thr, 8 warps 4x2, warp tile 32x64 --------
#define SROW    40
#define PART_B  (128 * SROW * 2)
#define STAGE_B (4 * PART_B)

__global__ void __launch_bounds__(256, 2)
gemm_mma(const bf16* __restrict__ Ah, const bf16* __restrict__ Al,
         const bf16* __restrict__ Bh, const bf16* __restrict__ Bl,
         float* __restrict__ C, int M, int N, int K, int ksl, int mode) {
    extern __shared__ char smem[];
    const uint32_t sb = smem_u32(smem);
    const int tid = threadIdx.x, lane = tid & 31, wid = tid >> 5;
    const int m0 = blockIdx.y * 128, n0 = blockIdx.x * 128;
    const int wm = wid & 3, wn = wid >> 2;
    const int ks = blockIdx.z * ksl;

    const bf16* gp[4] = { Ah + (size_t)m0 * K + ks, Al + (size_t)m0 * K + ks,
                          Bh + (size_t)n0 * K + ks, Bl + (size_t)n0 * K + ks };
    const int r0c = tid >> 2, c0c = (tid & 3) * 8;

    float acc[2][8][4];
    #pragma unroll
    for (int i = 0; i < 2; i++)
        #pragma unroll
        for (int j = 0; j < 8; j++)
            #pragma unroll
            for (int k = 0; k < 4; k++) acc[i][j][k] = 0.f;

    const int kt = ksl >> 5;
    #pragma unroll
    for (int s = 0; s < 2; s++) {
        const int k0 = s * 32;
        const uint32_t st = sb + s * STAGE_B;
        #pragma unroll
        for (int p = 0; p < 4; p++) {
            CP_ASYNC(st + p * PART_B + r0c * 80 + c0c * 2, gp[p] + (size_t)r0c * K + k0 + c0c);
            CP_ASYNC(st + p * PART_B + (r0c + 64) * 80 + c0c * 2, gp[p] + (size_t)(r0c + 64) * K + k0 + c0c);
        }
        CP_COMMIT();
    }

    const int rA = lane & 15, gA = lane >> 4;
    const uint32_t aoff = (uint32_t)(((wm * 32 + rA) * SROW + gA * 8) * 2);
    const int rB = lane & 7, gB = lane >> 3;
    const uint32_t boff = (uint32_t)(((wn * 64 + (gB & 1) * 8 + rB) * SROW + (gB >> 1) * 8) * 2);

    for (int it = 0; it < kt; it++) {
        CP_WAIT1();
        __syncthreads();
        const uint32_t st = sb + (it & 1) * STAGE_B;
        const uint32_t sAh = st, sAl = st + PART_B, sBh = st + 2 * PART_B, sBl = st + 3 * PART_B;
        #pragma unroll
        for (int k2 = 0; k2 < 2; k2++) {
            const uint32_t ko = k2 * 32;
            uint32_t ah[2][4], al[2][4];
            #pragma unroll
            for (int mt = 0; mt < 2; mt++) {
                LDM_X4(ah[mt][0], ah[mt][1], ah[mt][2], ah[mt][3], sAh + aoff + mt * (16 * SROW * 2) + ko);
                LDM_X4(al[mt][0], al[mt][1], al[mt][2], al[mt][3], sAl + aoff + mt * (16 * SROW * 2) + ko);
            }
            #pragma unroll
            for (int ng = 0; ng < 4; ng++) {
                uint32_t bh[4], bl[4];
                LDM_X4(bh[0], bh[1], bh[2], bh[3], sBh + boff + ng * (16 * SROW * 2) + ko);
                LDM_X4(bl[0], bl[1], bl[2], bl[3], sBl + boff + ng * (16 * SROW * 2) + ko);
                #pragma unroll
                for (int mt = 0; mt < 2; mt++) {
                    #pragma unroll
                    for (int h = 0; h < 2; h++) {
                        float* d = acc[mt][ng * 2 + h];
                        MMA(d, ah[mt], bh[h], bh[2 + h]);
                        MMA(d, ah[mt], bl[h], bl[2 + h]);
                        MMA(d, al[mt], bh[h], bh[2 + h]);
                    }
                }
            }
        }
        __syncthreads();
        const int kn = it + 2;
        if (kn < kt) {
            const int k0 = kn * 32;
            const uint32_t s2 = sb + (it & 1) * STAGE_B;
            #pragma unroll
            for (int p = 0; p < 4; p++) {
                CP_ASYNC(s2 + p * PART_B + r0c * 80 + c0c * 2, gp[p] + (size_t)r0c * K + k0 + c0c);
                CP_ASYNC(s2 + p * PART_B + (r0c + 64) * 80 + c0c * 2, gp[p] + (size_t)(r0c + 64) * K + k0 + c0c);
            }
        }
        CP_COMMIT();
    }

    if (mode == 0) {
        float* Cz = C + (size_t)blockIdx.z * M * N;
        #pragma unroll
        for (int mt = 0; mt < 2; mt++) {
            const int row = m0 + wm * 32 + mt * 16 + (lane >> 2);
            #pragma unroll
            for (int nt = 0; nt < 8; nt++) {
                const int col = n0 + wn * 64 + nt * 8 + (lane & 3) * 2;
                if (col < N) {
                    *(float2*)&Cz[(size_t)row * N + col] = make_float2(acc[mt][nt][0], acc[mt][nt][1]);
                    *(float2*)&Cz[(size_t)(row + 8) * N + col] = make_float2(acc[mt][nt][2], acc[mt][nt][3]);
                }
            }
        }
    } else if (mode == 1) {
        #pragma unroll
        for (int mt = 0; mt < 2; mt++) {
            const int row = m0 + wm * 32 + mt * 16 + (lane >> 2);
            const int b = row >> 7, t = row & 127;
            #pragma unroll
            for (int nt = 0; nt < 8; nt++) {
                const int c = n0 + wn * 64 + nt * 8 + (lane & 3) * 2;
                const int h = c / 192, d = c - h * 192;
                const size_t base = ((size_t)((b * 32 + h) * 128 + t)) * 192 + d;
                unsigned short h0, l0, h1, l1;
                split_bf16(acc[mt][nt][0], h0, l0); split_bf16(acc[mt][nt][1], h1, l1);
                *(uint32_t*)((unsigned short*)g_qp_h + base) = h0 | ((uint32_t)h1 << 16);
                *(uint32_t*)((unsigned short*)g_qp_l + base) = l0 | ((uint32_t)l1 << 16);
                split_bf16(acc[mt][nt][2], h0, l0); split_bf16(acc[mt][nt][3], h1, l1);
                *(uint32_t*)((unsigned short*)g_qp_h + base + 8 * 192) = h0 | ((uint32_t)h1 << 16);
                *(uint32_t*)((unsigned short*)g_qp_l + base + 8 * 192) = l0 | ((uint32_t)l1 << 16);
            }
        }
    } else {
        // kv: tile is pure K-block (n0%256==0) or pure V-block (n0%256==128)
        const int h = n0 >> 8;
        const int b = m0 >> 7;
        if ((n0 & 255) == 0) {
            #pragma unroll
            for (int mt = 0; mt < 2; mt++) {
                const int t = (wm * 32 + mt * 16 + (lane >> 2)) & 127;
                #pragma unroll
                for (int nt = 0; nt < 8; nt++) {
                    const int d = wn * 64 + nt * 8 + (lane & 3) * 2;
                    const size_t base = ((size_t)((b * 32 + h) * 128 + t)) * 192 + d;
                    unsigned short h0, l0, h1, l1;
                    split_bf16(acc[mt][nt][0], h0, l0); split_bf16(acc[mt][nt][1], h1, l1);
                    *(uint32_t*)((unsigned short*)g_kp_h + base) = h0 | ((uint32_t)h1 << 16);
                    *(uint32_t*)((unsigned short*)g_kp_l + base) = l0 | ((uint32_t)l1 << 16);
                    split_bf16(acc[mt][nt][2], h0, l0); split_bf16(acc[mt][nt][3], h1, l1);
                    *(uint32_t*)((unsigned short*)g_kp_h + base + 8 * 192) = h0 | ((uint32_t)h1 << 16);
                    *(uint32_t*)((unsigned short*)g_kp_l + base + 8 * 192) = l0 | ((uint32_t)l1 << 16);
                }
            }
        } else {
            __syncthreads();
            float* T = (float*)smem;  // [128 dv][132]
            #pragma unroll
            for (int mt = 0; mt < 2; mt++) {
                const int tl = wm * 32 + mt * 16 + (lane >> 2);
                #pragma unroll
                for (int nt = 0; nt < 8; nt++) {
                    const int dv = wn * 64 + nt * 8 + (lane & 3) * 2;
                    T[(dv) * 132 + tl]         = acc[mt][nt][0];
                    T[(dv + 1) * 132 + tl]     = acc[mt][nt][1];
                    T[(dv) * 132 + tl + 8]     = acc[mt][nt][2];
                    T[(dv + 1) * 132 + tl + 8] = acc[mt][nt][3];
                }
            }
            __syncthreads();
            const size_t vb = ((size_t)((b * 32 + h) * 128)) * 128;
            for (int i = tid; i < 4096; i += 256) {
                const int dv = i >> 5, tq = (i & 31) * 4;
                const float* r = T + dv * 132 + tq;
                unsigned short h0, l0, h1, l1, h2, l2, h3, l3;
                split_bf16(r[0], h0, l0); split_bf16(r[1], h1, l1);
                split_bf16(r[2], h2, l2); split_bf16(r[3], h3, l3);
                const size_t o = vb + (size_t)dv * 128 + tq;
                *(uint2*)((unsigned short*)g_vT_h + o) = make_uint2(h0 | ((uint32_t)h1 << 16), h2 | ((uint32_t)h3 << 16));
                *(uint2*)((unsigned short*)g_vT_l + o) = make_uint2(l0 | ((uint32_t)l1 << 16), l2 | ((uint32_t)l3 << 16));
            }
        }
    }
}

// ---------------- small kernels ----------------
__global__ void __launch_bounds__(256) add2(const float* __restrict__ a,
                                            const float* __restrict__ b,
                                            float* __restrict__ o, int n) {
    const int i = (blockIdx.x * 256 + threadIdx.x) * 4;
    if (i >= n) return;
    float4 va = *(const float4*)(a + i);
    float4 vb = *(const float4*)(b + i);
    *(float4*)(o + i) = make_float4(va.x + vb.x, va.y + vb.y, va.z + vb.z, va.w + vb.w);
}

__global__ void __launch_bounds__(256) act_pack(const float* __restrict__ in,
                                                bf16* __restrict__ hi, bf16* __restrict__ lo, int n) {
    const int i = (blockIdx.x * 256 + threadIdx.x) * 4;
    if (i >= n) return;
    float4 v = *(const float4*)(in + i);
    unsigned short h[4], l[4];
    split_bf16(v.x, h[0], l[0]); split_bf16(v.y, h[1], l[1]);
    split_bf16(v.z, h[2], l[2]); split_bf16(v.w, h[3], l[3]);
    *(uint2*)((unsigned short*)hi + i) = make_uint2(h[0] | ((uint32_t)h[1] << 16), h[2] | ((uint32_t)h[3] << 16));
    *(uint2*)((unsigned short*)lo + i) = make_uint2(l[0] | ((uint32_t)l[1] << 16), l[2] | ((uint32_t)l[3] << 16));
}

__global__ void __launch_bounds__(256) wt_pack2(const float* __restrict__ W,
                                                bf16* __restrict__ oh, bf16* __restrict__ ol,
                                                int K, int N) {
    __shared__ float tile[128][33];
    const int n0 = blockIdx.x * 32, k0 = blockIdx.y * 128;
    const int tid = threadIdx.x;
    const int lr = tid >> 3, lc = (tid & 7) * 4;
    if (n0 < N) {
        #pragma unroll
        for (int j = 0; j < 4; j++) {
            const int k = k0 + lr + j * 32;
            float4 v = *(const float4*)(W + (size_t)k * N + n0 + lc);
            tile[lr + j * 32][lc] = v.x; tile[lr + j * 32][lc + 1] = v.y;
            tile[lr + j * 32][lc + 2] = v.z; tile[lr + j * 32][lc + 3] = v.w;
        }
    } else {
        #pragma unroll
        for (int j = 0; j < 4; j++) {
            tile[lr + j * 32][lc] = 0.f; tile[lr + j * 32][lc + 1] = 0.f;
            tile[lr + j * 32][lc + 2] = 0.f; tile[lr + j * 32][lc + 3] = 0.f;
        }
    }
    __syncthreads();
    const int nl = tid >> 3, kk = (tid & 7) * 16;
    const size_t ob = (size_t)(n0 + nl) * K + k0 + kk;
    #pragma unroll
    for (int i = 0; i < 8; i++) {
        unsigned short h0, l0, h1, l1;
        split_bf16(tile[kk + 2 * i][nl], h0, l0);
        split_bf16(tile[kk + 2 * i + 1][nl], h1, l1);
        *(uint32_t*)((unsigned short*)oh + ob + 2 * i) = h0 | ((uint32_t)h1 << 16);
        *(uint32_t*)((unsigned short*)ol + ob + 2 * i) = l0 | ((uint32_t)l1 << 16);
    }
}

__global__ void __launch_bounds__(256) rmsnorm_pack(const float* __restrict__ in,
                                                    const float* __restrict__ w,
                                                    bf16* __restrict__ hi, bf16* __restrict__ lo,
                                                    int ncols, int ld, int poff) {
    const int row = blockIdx.x;
    const float* p0 = in + (size_t)row * ld;
    const float* p1 = p0 + (size_t)poff;
    float ss = 0.f;
    for (int i = threadIdx.x; i < ncols; i += 256) { float v = p0[i] + p1[i]; ss += v * v; }
    __shared__ float red[256];
    red[threadIdx.x] = ss; __syncthreads();
    for (int off = 128; off > 0; off >>= 1) {
        if (threadIdx.x < off) red[threadIdx.x] += red[threadIdx.x + off];
        __syncthreads();
    }
    const float scale = rsqrtf(red[0] / (float)ncols + 1e-6f);
    for (int i = threadIdx.x; i < ncols; i += 256) {
        unsigned short h, l;
        split_bf16((p0[i] + p1[i]) * scale * w[i], h, l);
        ((unsigned short*)hi)[(size_t)row * ncols + i] = h;
        ((unsigned short*)lo)[(size_t)row * ncols + i] = l;
    }
}

__global__ void __launch_bounds__(256) kv_post_pack(const float* __restrict__ w,
                                                    const float* __restrict__ freqs) {
    const int tg = blockIdx.x;
    const int b = tg >> 7, s = tg & 127;
    const float* p0 = g_qkva + (size_t)tg * NC1 + QLORA;
    const float* p1 = p0 + (size_t)NTOK * NC1;
    float ss = 0.f;
    for (int i = threadIdx.x; i < KVLORA; i += 256) { float v = p0[i] + p1[i]; ss += v * v; }
    __shared__ float red[256];
    red[threadIdx.x] = ss; __syncthreads();
    for (int off = 128; off > 0; off >>= 1) {
        if (threadIdx.x < off) red[threadIdx.x] += red[threadIdx.x + off];
        __syncthreads();
    }
    const float scale = rsqrtf(red[0] / (float)KVLORA + 1e-6f);
    for (int i = threadIdx.x; i < KVLORA; i += 256) {
        unsigned short h, l;
        split_bf16((p0[i] + p1[i]) * scale * w[i], h, l);
        ((unsigned short*)g_kvn_h)[(size_t)tg * KVLORA + i] = h;
        ((unsigned short*)g_kvn_l)[(size_t)tg * KVLORA + i] = l;
    }
    if (threadIdx.x < ROPE) {
        const int d = threadIdx.x;
        unsigned short h, l;
        split_bf16((p0[KVLORA + d] + p1[KVLORA + d]) * freqs[s * (ROPE / 2) + (d >> 1)], h, l);
        #pragma unroll 4
        for (int hh = 0; hh < NHEADS; hh++) {
            const size_t a = ((size_t)((b * 32 + hh) * 128 + s)) * 192 + 128 + d;
            ((unsigned short*)g_kp_h)[a] = h;
            ((unsigned short*)g_kp_l)[a] = l;
        }
    }
}

// ---------------- fused flash attention per (b,h) ----------------
#define VBASE  81920
#define PLBASE 34816
#define REDOFF 122880
#define PSTR   136
#define FLASH_SMEM 124928

__global__ void __launch_bounds__(256, 1) flash_attn() {
    extern __shared__ char smem[];
    const uint32_t sb = smem_u32(smem);
    const int tid = threadIdx.x, lane = tid & 31, wid = tid >> 5;
    const int wm = wid & 3, wn = wid >> 2;
    const int bh = blockIdx.x, b = bh >> 5, h = bh & 31;

    const bf16* gqh = g_qp_h + (size_t)bh * SEQ * QKH;
    const bf16* gql = g_qp_l + (size_t)bh * SEQ * QKH;
    const bf16* gkh = g_kp_h + (size_t)bh * SEQ * QKH;
    const bf16* gkl = g_kp_l + (size_t)bh * SEQ * QKH;
    const bf16* gvh = g_vT_h + (size_t)bh * VH * SEQ;
    const bf16* gvl = g_vT_l + (size_t)bh * VH * SEQ;
    const bf16* gp[4] = { gqh, gql, gkh, gkl };

    const int r0c = tid >> 2, c0c = (tid & 3) * 8;

    #pragma unroll
    for (int s = 0; s < 2; s++) {
        const int k0 = s * 32;
        const uint32_t st = sb + s * STAGE_B;
        #pragma unroll
        for (int p = 0; p < 4; p++) {
            CP_ASYNC(st + p * PART_B + r0c * 80 + c0c * 2, gp[p] + (size_t)r0c * QKH + k0 + c0c);
            CP_ASYNC(st + p * PART_B + (r0c + 64) * 80 + c0c * 2, gp[p] + (size_t)(r0c + 64) * QKH + k0 + c0c);
        }
        const uint32_t vst = sb + VBASE + s * 20480;
        CP_ASYNC(vst + r0c * 80 + c0c * 2, gvh + (size_t)r0c * SEQ + k0 + c0c);
        CP_ASYNC(vst + (r0c + 64) * 80 + c0c * 2, gvh + (size_t)(r0c + 64) * SEQ + k0 + c0c);
        CP_ASYNC(vst + 10240 + r0c * 80 + c0c * 2, gvl + (size_t)r0c * SEQ + k0 + c0c);
        CP_ASYNC(vst + 10240 + (r0c + 64) * 80 + c0c * 2, gvl + (size_t)(r0c + 64) * SEQ + k0 + c0c);
        CP_COMMIT();
    }

    const int rA = lane & 15, gA = lane >> 4;
    const uint32_t aoff = (uint32_t)(((wm * 32 + rA) * SROW + gA * 8) * 2);
    const int rB = lane & 7, gB = lane >> 3;
    const uint32_t boff = (uint32_t)(((wn * 64 + (gB & 1) * 8 + rB) * SROW + (gB >> 1) * 8) * 2);

    float acc[2][8][4];
    #pragma unroll
    for (int i = 0; i < 2; i++)
        #pragma unroll
        for (int j = 0; j < 8; j++)
            #pragma unroll
            for (int k = 0; k < 4; k++) acc[i][j][k] = 0.f;

    for (int it = 0; it < 6; it++) {
        CP_WAIT1();
        __syncthreads();
        const uint32_t st = sb + (it & 1) * STAGE_B;
        const uint32_t sAh = st, sAl = st + PART_B, sBh = st + 2 * PART_B, sBl = st + 3 * PART_B;
        #pragma unroll
        for (int k2 = 0; k2 < 2; k2++) {
            const uint32_t ko = k2 * 32;
            uint32_t ah[2][4], al[2][4];
            #pragma unroll
            for (int mt = 0; mt < 2; mt++) {
                LDM_X4(ah[mt][0], ah[mt][1], ah[mt][2], ah[mt][3], sAh + aoff + mt * (16 * SROW * 2) + ko);
                LDM_X4(al[mt][0], al[mt][1], al[mt][2], al[mt][3], sAl + aoff + mt * (16 * SROW * 2) + ko);
            }
            #pragma unroll
            for (int ng = 0; ng < 4; ng++) {
                uint32_t bh2[4], bl2[4];
                LDM_X4(bh2[0], bh2[1], bh2[2], bh2[3], sBh + boff + ng * (16 * SROW * 2) + ko);
                LDM_X4(bl2[0], bl2[1], bl2[2], bl2[3], sBl + boff + ng * (16 * SROW * 2) + ko);
                #pragma unroll
                for (int mt = 0; mt < 2; mt++) {
                    #pragma unroll
                    for (int hh = 0; hh < 2; hh++) {
                        float* d = acc[mt][ng * 2 + hh];
                        MMA(d, ah[mt], bh2[hh], bh2[2 + hh]);
                        MMA(d, ah[mt], bl2[hh], bl2[2 + hh]);
                        MMA(d, al[mt], bh2[hh], bh2[2 + hh]);
                    }
                }
            }
        }
        __syncthreads();
        const int kn = it + 2;
        if (kn < 6) {
            const int k0 = kn * 32;
            const uint32_t s2 = sb + (it & 1) * STAGE_B;
            #pragma unroll
            for (int p = 0; p < 4; p++) {
                CP_ASYNC(s2 + p * PART_B + r0c * 80 + c0c * 2, gp[p] + (size_t)r0c * QKH + k0 + c0c);
                CP_ASYNC(s2 + p * PART_B + (r0c + 64) * 80 + c0c * 2, gp[p] + (size_t)(r0c + 64) * QKH + k0 + c0c);
            }
        }
        CP_COMMIT();
    }
    CP_WAIT0();
    __syncthreads();

    float* RMAX = (float*)(smem + REDOFF);
    float* RSUM = (float*)(smem + REDOFF + 1024);
    const float scl = 0.07216878364870323f;
    const int rbase = wm * 32 + (lane >> 2);
    const int cbase = wn * 64 + (lane & 3) * 2;

    #pragma unroll
    for (int mt = 0; mt < 2; mt++)
        #pragma unroll
        for (int nt = 0; nt < 8; nt++)
            #pragma unroll
            for (int k = 0; k < 4; k++) {
                const int r = rbase + mt * 16 + (k >> 1) * 8;
                const int c = cbase + nt * 8 + (k & 1);
                float v = acc[mt][nt][k] * scl;
                acc[mt][nt][k] = (c > r) ? -INFINITY : v;
            }

    #pragma unroll
    for (int mt = 0; mt < 2; mt++)
        #pragma unroll
        for (int hf = 0; hf < 2; hf++) {
            float m = -INFINITY;
            #pragma unroll
            for (int nt = 0; nt < 8; nt++)
                m = fmaxf(m, fmaxf(acc[mt][nt][hf * 2], acc[mt][nt][hf * 2 + 1]));
            m = fmaxf(m, __shfl_xor_sync(0xffffffffu, m, 1));
            m = fmaxf(m, __shfl_xor_sync(0xffffffffu, m, 2));
            if ((lane & 3) == 0) RMAX[wn * 128 + rbase + mt * 16 + hf * 8] = m;
        }
    __syncthreads();
    #pragma unroll
    for (int mt = 0; mt < 2; mt++)
        #pragma unroll
        for (int hf = 0; hf < 2; hf++) {
            const int r = rbase + mt * 16 + hf * 8;
            const float m = fmaxf(RMAX[r], RMAX[128 + r]);
            float s = 0.f;
            #pragma unroll
            for (int nt = 0; nt < 8; nt++) {
                float p0 = expf(acc[mt][nt][hf * 2] - m);
                float p1 = expf(acc[mt][nt][hf * 2 + 1] - m);
                acc[mt][nt][hf * 2] = p0; acc[mt][nt][hf * 2 + 1] = p1;
                s += p0 + p1;
            }
            s += __shfl_xor_sync(0xffffffffu, s, 1);
            s += __shfl_xor_sync(0xffffffffu, s, 2);
            if ((lane & 3) == 0) RSUM[wn * 128 + r] = s;
        }
    #pragma unroll
    for (int mt = 0; mt < 2; mt++)
        #pragma unroll
        for (int nt = 0; nt < 8; nt++)
            #pragma unroll
            for (int hf = 0; hf < 2; hf++) {
                const int r = rbase + mt * 16 + hf * 8;
                const int c = cbase + nt * 8;
                unsigned short h0, l0, h1, l1;
                split_bf16(acc[mt][nt][hf * 2], h0, l0);
                split_bf16(acc[mt][nt][hf * 2 + 1], h1, l1);
                *(uint32_t*)(smem + (r * PSTR + c) * 2) = h0 | ((uint32_t)h1 << 16);
                *(uint32_t*)(smem + PLBASE + (r * PSTR + c) * 2) = l0 | ((uint32_t)l1 << 16);
            }
    __syncthreads();

    const uint32_t aoffP = (uint32_t)(((wm * 32 + rA) * PSTR + gA * 8) * 2);
    float o[2][8][4];
    #pragma unroll
    for (int i = 0; i < 2; i++)
        #pragma unroll
        for (int j = 0; j < 8; j++)
            #pragma unroll
            for (int k = 0; k < 4; k++) o[i][j][k] = 0.f;

    for (int it = 0; it < 4; it++) {
        CP_WAIT1();
        __syncthreads();
        const uint32_t vst = sb + VBASE + (it & 1) * 20480;
        #pragma unroll
        for (int k2 = 0; k2 < 2; k2++) {
            const uint32_t kP = (it * 32 + k2 * 16) * 2;
            const uint32_t kV = k2 * 32;
            uint32_t ph[2][4], pl[2][4];
            #pragma unroll
            for (int mt = 0; mt < 2; mt++) {
                LDM_X4(ph[mt][0], ph[mt][1], ph[mt][2], ph[mt][3], sb + aoffP + mt * (16 * PSTR * 2) + kP);
                LDM_X4(pl[mt][0], pl[mt][1], pl[mt][2], pl[mt][3], sb + PLBASE + aoffP + mt * (16 * PSTR * 2) + kP);
            }
            #pragma unroll
            for (int ng = 0; ng < 4; ng++) {
                uint32_t vh[4], vl[4];
                LDM_X4(vh[0], vh[1], vh[2], vh[3], vst + boff + ng * (16 * SROW * 2) + kV);
                LDM_X4(vl[0], vl[1], vl[2], vl[3], vst + 10240 + boff + ng * (16 * SROW * 2) + kV);
                #pragma unroll
                for (int mt = 0; mt < 2; mt++) {
                    #pragma unroll
                    for (int hh = 0; hh < 2; hh++) {
                        float* d = o[mt][ng * 2 + hh];
                        MMA(d, ph[mt], vh[hh], vh[2 + hh]);
                        MMA(d, ph[mt], vl[hh], vl[2 + hh]);
                        MMA(d, pl[mt], vh[hh], vh[2 + hh]);
                    }
                }
            }
        }
        __syncthreads();
        const int kn = it + 2;
        if (kn < 4) {
            const int k0 = kn * 32;
            const uint32_t v2 = sb + VBASE + (it & 1) * 20480;
            CP_ASYNC(v2 + r0c * 80 + c0c * 2, gvh + (size_t)r0c * SEQ + k0 + c0c);
            CP_ASYNC(v2 + (r0c + 64) * 80 + c0c * 2, gvh + (size_t)(r0c + 64) * SEQ + k0 + c0c);
            CP_ASYNC(v2 + 10240 + r0c * 80 + c0c * 2, gvl + (size_t)r0c * SEQ + k0 + c0c);
            CP_ASYNC(v2 + 10240 + (r0c + 64) * 80 + c0c * 2, gvl + (size_t)(r0c + 64) * SEQ + k0 + c0c);
        }
        CP_COMMIT();
    }

    #pragma unroll
    for (int mt = 0; mt < 2; mt++) {
        float inv[2];
        #pragma unroll
        for (int hf = 0; hf < 2; hf++) {
            const int r = rbase + mt * 16 + hf * 8;
            inv[hf] = 1.f / (RSUM[r] + RSUM[128 + r]);
        }
        #pragma unroll
        for (int nt = 0; nt < 8; nt++) {
            const int c = cbase + nt * 8;
            #pragma unroll
            for (int hf = 0; hf < 2; hf++) {
                const int r = rbase + mt * 16 + hf * 8;
                const size_t off = (size_t)(b * SEQ + r) * DIM + h * VH + c;
                unsigned short h0, l0, h1, l1;
                split_bf16(o[mt][nt][hf * 2] * inv[hf], h0, l0);
                split_bf16(o[mt][nt][hf * 2 + 1] * inv[hf], h1, l1);
                *(uint32_t*)((unsigned short*)g_ao_h + off) = h0 | ((uint32_t)h1 << 16);
                *(uint32_t*)((unsigned short*)g_ao_l + off) = l0 | ((uint32_t)l1 << 16);
            }
        }
    }
}

// ---------------- launch ----------------
extern "C" void kernel_launch(void* const* d_in, const int* in_sizes, int n_in,
                              void* d_out, int out_size) {
    const float* x       = (const float*)d_in[0];
    const float* freqs   = (const float*)d_in[1];
    const float* wq_a    = (const float*)d_in[2];
    const float* q_norm  = (const float*)d_in[3];
    const float* wq_b    = (const float*)d_in[4];
    const float* wkv_a   = (const float*)d_in[5];
    const float* kv_norm = (const float*)d_in[6];
    const float* wkv_b   = (const float*)d_in[7];
    const float* wo      = (const float*)d_in[8];
    float* out = (float*)d_out;

    const int GEMM_SMEM = 2 * STAGE_B;
    cudaFuncSetAttribute(gemm_mma, cudaFuncAttributeMaxDynamicSharedMemorySize, GEMM_SMEM);
    cudaFuncSetAttribute(flash_attn, cudaFuncAttributeMaxDynamicSharedMemorySize, FLASH_SMEM);

    float *qkva, *out2;
    bf16 *xh, *xl, *qnh, *qnl, *kvnh, *kvnl, *aoh, *aol;
    bf16 *wch, *wcl, *wqbh, *wqbl, *wkvbh, *wkvbl, *woh, *wol;
    cudaGetSymbolAddress((void**)&qkva, g_qkva);
    cudaGetSymbolAddress((void**)&out2, g_out2);
    cudaGetSymbolAddress((void**)&xh,   g_x_h);   cudaGetSymbolAddress((void**)&xl,   g_x_l);
    cudaGetSymbolAddress((void**)&qnh,  g_qn_h);  cudaGetSymbolAddress((void**)&qnl,  g_qn_l);
    cudaGetSymbolAddress((void**)&kvnh, g_kvn_h); cudaGetSymbolAddress((void**)&kvnl, g_kvn_l);
    cudaGetSymbolAddress((void**)&aoh,  g_ao_h);  cudaGetSymbolAddress((void**)&aol,  g_ao_l);
    cudaGetSymbolAddress((void**)&wch,  g_wc_h);  cudaGetSymbolAddress((void**)&wcl,  g_wc_l);
    cudaGetSymbolAddress((void**)&wqbh,  g_wqbT_h);  cudaGetSymbolAddress((void**)&wqbl,  g_wqbT_l);
    cudaGetSymbolAddress((void**)&wkvbh, g_wkvbT_h); cudaGetSymbolAddress((void**)&wkvbl, g_wkvbT_l);
    cudaGetSymbolAddress((void**)&woh,   g_woT_h);   cudaGetSymbolAddress((void**)&wol,   g_woT_l);

    // #1-3 packs, #4 = gemm1 split-K2 (profiled slot)
    act_pack<<<NTOK * DIM / 4 / 256, 256>>>(x, xh, xl, NTOK * DIM);
    wt_pack2<<<dim3(QLORA / 32, DIM / 128), 256>>>(wq_a, wch, wcl, DIM, QLORA);
    wt_pack2<<<dim3(NKVP / 32, DIM / 128), 256>>>(wkv_a, wch + (size_t)QLORA * DIM, wcl + (size_t)QLORA * DIM, DIM, NKV);

    gemm_mma<<<dim3(NC1 / 128, NTOK / 128, 2), 256, GEMM_SMEM>>>(xh, xl, wch, wcl, qkva, NTOK, NC1, DIM, DIM / 2, 0);

    rmsnorm_pack<<<NTOK, 256>>>(qkva, q_norm, qnh, qnl, QLORA, NC1, NTOK * NC1);
    kv_post_pack<<<NTOK, 256>>>(kv_norm, freqs);
    wt_pack2<<<dim3(NQB / 32, QLORA / 128), 256>>>(wq_b, wqbh, wqbl, QLORA, NQB);
    wt_pack2<<<dim3(NKVB / 32, KVLORA / 128), 256>>>(wkv_b, wkvbh, wkvbl, KVLORA, NKVB);

    gemm_mma<<<dim3(NQB / 128, NTOK / 128), 256, GEMM_SMEM>>>(qnh, qnl, wqbh, wqbl, nullptr, NTOK, NQB, QLORA, QLORA, 1);
    gemm_mma<<<dim3(NKVB / 128, NTOK / 128), 256, GEMM_SMEM>>>(kvnh, kvnl, wkvbh, wkvbl, nullptr, NTOK, NKVB, KVLORA, KVLORA, 2);

    flash_attn<<<BATCH * NHEADS, 256, FLASH_SMEM>>>();

    wt_pack2<<<dim3(DIM / 32, DIM / 128), 256>>>(wo, woh, wol, DIM, DIM);
    gemm_mma<<<dim3(DIM / 128, NTOK / 128, 2), 256, GEMM_SMEM>>>(aoh, aol, woh, wol, out2, NTOK, DIM, DIM, DIM / 2, 0);
    add2<<<NTOK * DIM / 4 / 256, 256>>>(out2, out2 + (size_t)NTOK * DIM, out, NTOK * DIM);
}

// round 14
// speedup vs baseline: 1.9986x; 1.0024x over previous
#include <cuda_runtime.h>
#include <cuda_bf16.h>
#include <math.h>
#include <stdint.h>

#define NHEADS 32
#define QKH    192
#define NOPE   128
#define ROPE   64
#define VH     128
#define KVLORA 512
#define DIM    4096
#define QLORA  1536
#define BATCH  8
#define SEQ    128
#define NTOK   1024
#define NKV    576
#define NKVP   640
#define NQB    6144
#define NKVB   8192
#define NC1    2176

typedef __nv_bfloat16 bf16;

// ---------------- scratch ----------------
__device__ float g_qkva[2 * NTOK * NC1];      // split-K partials
__device__ float g_out2[2 * NTOK * DIM];      // wo split-K partials

__device__ bf16 g_wc_h   [NC1 * DIM],     g_wc_l   [NC1 * DIM];
__device__ bf16 g_wqbT_h [NQB * QLORA],   g_wqbT_l [NQB * QLORA];
__device__ bf16 g_wkvbT_h[NKVB * KVLORA], g_wkvbT_l[NKVB * KVLORA];
__device__ bf16 g_woT_h  [DIM * DIM],     g_woT_l  [DIM * DIM];

__device__ bf16 g_x_h  [NTOK * DIM],    g_x_l  [NTOK * DIM];
__device__ bf16 g_qn_h [NTOK * QLORA],  g_qn_l [NTOK * QLORA];
__device__ bf16 g_kvn_h[NTOK * KVLORA], g_kvn_l[NTOK * KVLORA];
__device__ bf16 g_ao_h [NTOK * DIM],    g_ao_l [NTOK * DIM];

__device__ bf16 g_qp_h[BATCH * NHEADS * SEQ * QKH], g_qp_l[BATCH * NHEADS * SEQ * QKH];
__device__ bf16 g_kp_h[BATCH * NHEADS * SEQ * QKH], g_kp_l[BATCH * NHEADS * SEQ * QKH];
__device__ bf16 g_vT_h[BATCH * NHEADS * VH * SEQ],  g_vT_l[BATCH * NHEADS * VH * SEQ];

// ---------------- helpers ----------------
__device__ __forceinline__ uint32_t smem_u32(const void* p) {
    uint32_t a;
    asm("{ .reg .u64 t; cvta.to.shared.u64 t, %1; cvt.u32.u64 %0, t; }" : "=r"(a) : "l"(p));
    return a;
}
#define CP_ASYNC(dst, src) asm volatile("cp.async.cg.shared.global [%0], [%1], 16;" :: "r"(dst), "l"(src))
#define CP_COMMIT()        asm volatile("cp.async.commit_group;")
#define CP_WAIT1()         asm volatile("cp.async.wait_group 1;")
#define CP_WAIT0()         asm volatile("cp.async.wait_group 0;")

#define LDM_X4(r0, r1, r2, r3, a) \
    asm volatile("ldmatrix.sync.aligned.m8n8.x4.shared.b16 {%0,%1,%2,%3}, [%4];" \
        : "=r"(r0), "=r"(r1), "=r"(r2), "=r"(r3) : "r"(a))

#define MMA(d, a, b0, b1) \
    asm volatile("mma.sync.aligned.m16n8k16.row.col.f32.bf16.bf16.f32 " \
        "{%0,%1,%2,%3}, {%4,%5,%6,%7}, {%8,%9}, {%0,%1,%2,%3};" \
        : "+f"((d)[0]), "+f"((d)[1]), "+f"((d)[2]), "+f"((d)[3]) \
        : "r"((a)[0]), "r"((a)[1]), "r"((a)[2]), "r"((a)[3]), "r"(b0), "r"(b1))

__device__ __forceinline__ void split_bf16(float v, unsigned short& h, unsigned short& l) {
    bf16 hb = __float2bfloat16(v);
    h = __bfloat16_as_ushort(hb);
    l = __bfloat16_as_ushort(__float2bfloat16(v - __bfloat162float(hb)));
}

// ---------------- split-bf16 GEMM: 256 thr, 8 warps 4x2, warp tile 32x64 --------
#define SROW    40
#define PART_B  (128 * SROW * 2)
#define STAGE_B (4 * PART_B)

__global__ void __launch_bounds__(256, 2)
gemm_mma(const bf16* __restrict__ Ah, const bf16* __restrict__ Al,
         const bf16* __restrict__ Bh, const bf16* __restrict__ Bl,
         float* __restrict__ C, int M, int N, int K, int ksl, int mode) {
    extern __shared__ char smem[];
    const uint32_t sb = smem_u32(smem);
    const int tid = threadIdx.x, lane = tid & 31, wid = tid >> 5;
    const int m0 = blockIdx.y * 128, n0 = blockIdx.x * 128;
    const int wm = wid & 3, wn = wid >> 2;
    const int ks = blockIdx.z * ksl;

    const bf16* gp[4] = { Ah + (size_t)m0 * K + ks, Al + (size_t)m0 * K + ks,
                          Bh + (size_t)n0 * K + ks, Bl + (size_t)n0 * K + ks };
    const int r0c = tid >> 2, c0c = (tid & 3) * 8;

    float acc[2][8][4];
    #pragma unroll
    for (int i = 0; i < 2; i++)
        #pragma unroll
        for (int j = 0; j < 8; j++)
            #pragma unroll
            for (int k = 0; k < 4; k++) acc[i][j][k] = 0.f;

    const int kt = ksl >> 5;
    #pragma unroll
    for (int s = 0; s < 2; s++) {
        const int k0 = s * 32;
        const uint32_t st = sb + s * STAGE_B;
        #pragma unroll
        for (int p = 0; p < 4; p++) {
            CP_ASYNC(st + p * PART_B + r0c * 80 + c0c * 2, gp[p] + (size_t)r0c * K + k0 + c0c);
            CP_ASYNC(st + p * PART_B + (r0c + 64) * 80 + c0c * 2, gp[p] + (size_t)(r0c + 64) * K + k0 + c0c);
        }
        CP_COMMIT();
    }

    const int rA = lane & 15, gA = lane >> 4;
    const uint32_t aoff = (uint32_t)(((wm * 32 + rA) * SROW + gA * 8) * 2);
    const int rB = lane & 7, gB = lane >> 3;
    const uint32_t boff = (uint32_t)(((wn * 64 + (gB & 1) * 8 + rB) * SROW + (gB >> 1) * 8) * 2);

    for (int it = 0; it < kt; it++) {
        CP_WAIT1();
        __syncthreads();
        const uint32_t st = sb + (it & 1) * STAGE_B;
        const uint32_t sAh = st, sAl = st + PART_B, sBh = st + 2 * PART_B, sBl = st + 3 * PART_B;
        #pragma unroll
        for (int k2 = 0; k2 < 2; k2++) {
            const uint32_t ko = k2 * 32;
            uint32_t ah[2][4], al[2][4];
            #pragma unroll
            for (int mt = 0; mt < 2; mt++) {
                LDM_X4(ah[mt][0], ah[mt][1], ah[mt][2], ah[mt][3], sAh + aoff + mt * (16 * SROW * 2) + ko);
                LDM_X4(al[mt][0], al[mt][1], al[mt][2], al[mt][3], sAl + aoff + mt * (16 * SROW * 2) + ko);
            }
            #pragma unroll
            for (int ng = 0; ng < 4; ng++) {
                uint32_t bh[4], bl[4];
                LDM_X4(bh[0], bh[1], bh[2], bh[3], sBh + boff + ng * (16 * SROW * 2) + ko);
                LDM_X4(bl[0], bl[1], bl[2], bl[3], sBl + boff + ng * (16 * SROW * 2) + ko);
                #pragma unroll
                for (int mt = 0; mt < 2; mt++) {
                    #pragma unroll
                    for (int h = 0; h < 2; h++) {
                        float* d = acc[mt][ng * 2 + h];
                        MMA(d, ah[mt], bh[h], bh[2 + h]);
                        MMA(d, ah[mt], bl[h], bl[2 + h]);
                        MMA(d, al[mt], bh[h], bh[2 + h]);
                    }
                }
            }
        }
        __syncthreads();
        const int kn = it + 2;
        if (kn < kt) {
            const int k0 = kn * 32;
            const uint32_t s2 = sb + (it & 1) * STAGE_B;
            #pragma unroll
            for (int p = 0; p < 4; p++) {
                CP_ASYNC(s2 + p * PART_B + r0c * 80 + c0c * 2, gp[p] + (size_t)r0c * K + k0 + c0c);
                CP_ASYNC(s2 + p * PART_B + (r0c + 64) * 80 + c0c * 2, gp[p] + (size_t)(r0c + 64) * K + k0 + c0c);
            }
        }
        CP_COMMIT();
    }

    if (mode == 0) {
        float* Cz = C + (size_t)blockIdx.z * M * N;
        #pragma unroll
        for (int mt = 0; mt < 2; mt++) {
            const int row = m0 + wm * 32 + mt * 16 + (lane >> 2);
            #pragma unroll
            for (int nt = 0; nt < 8; nt++) {
                const int col = n0 + wn * 64 + nt * 8 + (lane & 3) * 2;
                if (col < N) {
                    *(float2*)&Cz[(size_t)row * N + col] = make_float2(acc[mt][nt][0], acc[mt][nt][1]);
                    *(float2*)&Cz[(size_t)(row + 8) * N + col] = make_float2(acc[mt][nt][2], acc[mt][nt][3]);
                }
            }
        }
    } else if (mode == 1) {
        #pragma unroll
        for (int mt = 0; mt < 2; mt++) {
            const int row = m0 + wm * 32 + mt * 16 + (lane >> 2);
            const int b = row >> 7, t = row & 127;
            #pragma unroll
            for (int nt = 0; nt < 8; nt++) {
                const int c = n0 + wn * 64 + nt * 8 + (lane & 3) * 2;
                const int h = c / 192, d = c - h * 192;
                const size_t base = ((size_t)((b * 32 + h) * 128 + t)) * 192 + d;
                unsigned short h0, l0, h1, l1;
                split_bf16(acc[mt][nt][0], h0, l0); split_bf16(acc[mt][nt][1], h1, l1);
                *(uint32_t*)((unsigned short*)g_qp_h + base) = h0 | ((uint32_t)h1 << 16);
                *(uint32_t*)((unsigned short*)g_qp_l + base) = l0 | ((uint32_t)l1 << 16);
                split_bf16(acc[mt][nt][2], h0, l0); split_bf16(acc[mt][nt][3], h1, l1);
                *(uint32_t*)((unsigned short*)g_qp_h + base + 8 * 192) = h0 | ((uint32_t)h1 << 16);
                *(uint32_t*)((unsigned short*)g_qp_l + base + 8 * 192) = l0 | ((uint32_t)l1 << 16);
            }
        }
    } else {
        // kv: tile is pure K-block (n0%256==0) or pure V-block (n0%256==128)
        const int h = n0 >> 8;
        const int b = m0 >> 7;
        if ((n0 & 255) == 0) {
            #pragma unroll
            for (int mt = 0; mt < 2; mt++) {
                const int t = (wm * 32 + mt * 16 + (lane >> 2)) & 127;
                #pragma unroll
                for (int nt = 0; nt < 8; nt++) {
                    const int d = wn * 64 + nt * 8 + (lane & 3) * 2;
                    const size_t base = ((size_t)((b * 32 + h) * 128 + t)) * 192 + d;
                    unsigned short h0, l0, h1, l1;
                    split_bf16(acc[mt][nt][0], h0, l0); split_bf16(acc[mt][nt][1], h1, l1);
                    *(uint32_t*)((unsigned short*)g_kp_h + base) = h0 | ((uint32_t)h1 << 16);
                    *(uint32_t*)((unsigned short*)g_kp_l + base) = l0 | ((uint32_t)l1 << 16);
                    split_bf16(acc[mt][nt][2], h0, l0); split_bf16(acc[mt][nt][3], h1, l1);
                    *(uint32_t*)((unsigned short*)g_kp_h + base + 8 * 192) = h0 | ((uint32_t)h1 << 16);
                    *(uint32_t*)((unsigned short*)g_kp_l + base + 8 * 192) = l0 | ((uint32_t)l1 << 16);
                }
            }
        } else {
            __syncthreads();
            float* T = (float*)smem;  // [128 dv][132]
            #pragma unroll
            for (int mt = 0; mt < 2; mt++) {
                const int tl = wm * 32 + mt * 16 + (lane >> 2);
                #pragma unroll
                for (int nt = 0; nt < 8; nt++) {
                    const int dv = wn * 64 + nt * 8 + (lane & 3) * 2;
                    T[(dv) * 132 + tl]         = acc[mt][nt][0];
                    T[(dv + 1) * 132 + tl]     = acc[mt][nt][1];
                    T[(dv) * 132 + tl + 8]     = acc[mt][nt][2];
                    T[(dv + 1) * 132 + tl + 8] = acc[mt][nt][3];
                }
            }
            __syncthreads();
            const size_t vb = ((size_t)((b * 32 + h) * 128)) * 128;
            for (int i = tid; i < 4096; i += 256) {
                const int dv = i >> 5, tq = (i & 31) * 4;
                const float* r = T + dv * 132 + tq;
                unsigned short h0, l0, h1, l1, h2, l2, h3, l3;
                split_bf16(r[0], h0, l0); split_bf16(r[1], h1, l1);
                split_bf16(r[2], h2, l2); split_bf16(r[3], h3, l3);
                const size_t o = vb + (size_t)dv * 128 + tq;
                *(uint2*)((unsigned short*)g_vT_h + o) = make_uint2(h0 | ((uint32_t)h1 << 16), h2 | ((uint32_t)h3 << 16));
                *(uint2*)((unsigned short*)g_vT_l + o) = make_uint2(l0 | ((uint32_t)l1 << 16), l2 | ((uint32_t)l3 << 16));
            }
        }
    }
}

// ---------------- small kernels ----------------
__global__ void __launch_bounds__(256) add2(const float* __restrict__ a,
                                            const float* __restrict__ b,
                                            float* __restrict__ o, int n) {
    const int i = (blockIdx.x * 256 + threadIdx.x) * 4;
    if (i >= n) return;
    float4 va = *(const float4*)(a + i);
    float4 vb = *(const float4*)(b + i);
    *(float4*)(o + i) = make_float4(va.x + vb.x, va.y + vb.y, va.z + vb.z, va.w + vb.w);
}

__global__ void __launch_bounds__(256) act_pack(const float* __restrict__ in,
                                                bf16* __restrict__ hi, bf16* __restrict__ lo, int n) {
    const int i = (blockIdx.x * 256 + threadIdx.x) * 4;
    if (i >= n) return;
    float4 v = *(const float4*)(in + i);
    unsigned short h[4], l[4];
    split_bf16(v.x, h[0], l[0]); split_bf16(v.y, h[1], l[1]);
    split_bf16(v.z, h[2], l[2]); split_bf16(v.w, h[3], l[3]);
    *(uint2*)((unsigned short*)hi + i) = make_uint2(h[0] | ((uint32_t)h[1] << 16), h[2] | ((uint32_t)h[3] << 16));
    *(uint2*)((unsigned short*)lo + i) = make_uint2(l[0] | ((uint32_t)l[1] << 16), l[2] | ((uint32_t)l[3] << 16));
}

__global__ void __launch_bounds__(256) wt_pack2(const float* __restrict__ W,
                                                bf16* __restrict__ oh, bf16* __restrict__ ol,
                                                int K, int N) {
    __shared__ float tile[128][33];
    const int n0 = blockIdx.x * 32, k0 = blockIdx.y * 128;
    const int tid = threadIdx.x;
    const int lr = tid >> 3, lc = (tid & 7) * 4;
    if (n0 < N) {
        #pragma unroll
        for (int j = 0; j < 4; j++) {
            const int k = k0 + lr + j * 32;
            float4 v = *(const float4*)(W + (size_t)k * N + n0 + lc);
            tile[lr + j * 32][lc] = v.x; tile[lr + j * 32][lc + 1] = v.y;
            tile[lr + j * 32][lc + 2] = v.z; tile[lr + j * 32][lc + 3] = v.w;
        }
    } else {
        #pragma unroll
        for (int j = 0; j < 4; j++) {
            tile[lr + j * 32][lc] = 0.f; tile[lr + j * 32][lc + 1] = 0.f;
            tile[lr + j * 32][lc + 2] = 0.f; tile[lr + j * 32][lc + 3] = 0.f;
        }
    }
    __syncthreads();
    const int nl = tid >> 3, kk = (tid & 7) * 16;
    const size_t ob = (size_t)(n0 + nl) * K + k0 + kk;
    #pragma unroll
    for (int i = 0; i < 8; i++) {
        unsigned short h0, l0, h1, l1;
        split_bf16(tile[kk + 2 * i][nl], h0, l0);
        split_bf16(tile[kk + 2 * i + 1][nl], h1, l1);
        *(uint32_t*)((unsigned short*)oh + ob + 2 * i) = h0 | ((uint32_t)h1 << 16);
        *(uint32_t*)((unsigned short*)ol + ob + 2 * i) = l0 | ((uint32_t)l1 << 16);
    }
}

__global__ void __launch_bounds__(256) rmsnorm_pack(const float* __restrict__ in,
                                                    const float* __restrict__ w,
                                                    bf16* __restrict__ hi, bf16* __restrict__ lo,
                                                    int ncols, int ld, int poff) {
    const int row = blockIdx.x;
    const float* p0 = in + (size_t)row * ld;
    const float* p1 = p0 + (size_t)poff;
    float ss = 0.f;
    for (int i = threadIdx.x; i < ncols; i += 256) { float v = p0[i] + p1[i]; ss += v * v; }
    __shared__ float red[256];
    red[threadIdx.x] = ss; __syncthreads();
    for (int off = 128; off > 0; off >>= 1) {
        if (threadIdx.x < off) red[threadIdx.x] += red[threadIdx.x + off];
        __syncthreads();
    }
    const float scale = rsqrtf(red[0] / (float)ncols + 1e-6f);
    for (int i = threadIdx.x; i < ncols; i += 256) {
        unsigned short h, l;
        split_bf16((p0[i] + p1[i]) * scale * w[i], h, l);
        ((unsigned short*)hi)[(size_t)row * ncols + i] = h;
        ((unsigned short*)lo)[(size_t)row * ncols + i] = l;
    }
}

__global__ void __launch_bounds__(256) kv_post_pack(const float* __restrict__ w,
                                                    const float* __restrict__ freqs) {
    const int tg = blockIdx.x;
    const int b = tg >> 7, s = tg & 127;
    const float* p0 = g_qkva + (size_t)tg * NC1 + QLORA;
    const float* p1 = p0 + (size_t)NTOK * NC1;
    float ss = 0.f;
    for (int i = threadIdx.x; i < KVLORA; i += 256) { float v = p0[i] + p1[i]; ss += v * v; }
    __shared__ float red[256];
    red[threadIdx.x] = ss; __syncthreads();
    for (int off = 128; off > 0; off >>= 1) {
        if (threadIdx.x < off) red[threadIdx.x] += red[threadIdx.x + off];
        __syncthreads();
    }
    const float scale = rsqrtf(red[0] / (float)KVLORA + 1e-6f);
    for (int i = threadIdx.x; i < KVLORA; i += 256) {
        unsigned short h, l;
        split_bf16((p0[i] + p1[i]) * scale * w[i], h, l);
        ((unsigned short*)g_kvn_h)[(size_t)tg * KVLORA + i] = h;
        ((unsigned short*)g_kvn_l)[(size_t)tg * KVLORA + i] = l;
    }
    if (threadIdx.x < ROPE) {
        const int d = threadIdx.x;
        unsigned short h, l;
        split_bf16((p0[KVLORA + d] + p1[KVLORA + d]) * freqs[s * (ROPE / 2) + (d >> 1)], h, l);
        #pragma unroll 4
        for (int hh = 0; hh < NHEADS; hh++) {
            const size_t a = ((size_t)((b * 32 + hh) * 128 + s)) * 192 + 128 + d;
            ((unsigned short*)g_kp_h)[a] = h;
            ((unsigned short*)g_kp_l)[a] = l;
        }
    }
}

// ---------------- fused flash attention per (b,h) ----------------
// smem layout: QK stages [0, 81920); P hi [0, 34816) + P lo [34816, 69632)
// (written after QK phase); V double-buffer [69632, 110592) (over dead QK
// stage-1 region, loaded only after P is stored); reductions [110592, 112640).
// 112640 B <= 113 KB -> 2 CTAs/SM.
#define VBASE  69632
#define PLBASE 34816
#define REDOFF 110592
#define PSTR   136
#define FLASH_SMEM 112640

__global__ void __launch_bounds__(256, 2) flash_attn() {
    extern __shared__ char smem[];
    const uint32_t sb = smem_u32(smem);
    const int tid = threadIdx.x, lane = tid & 31, wid = tid >> 5;
    const int wm = wid & 3, wn = wid >> 2;
    const int bh = blockIdx.x, b = bh >> 5, h = bh & 31;

    const bf16* gqh = g_qp_h + (size_t)bh * SEQ * QKH;
    const bf16* gql = g_qp_l + (size_t)bh * SEQ * QKH;
    const bf16* gkh = g_kp_h + (size_t)bh * SEQ * QKH;
    const bf16* gkl = g_kp_l + (size_t)bh * SEQ * QKH;
    const bf16* gvh = g_vT_h + (size_t)bh * VH * SEQ;
    const bf16* gvl = g_vT_l + (size_t)bh * VH * SEQ;
    const bf16* gp[4] = { gqh, gql, gkh, gkl };

    const int r0c = tid >> 2, c0c = (tid & 3) * 8;

    // prologue: QK stages 0,1 only (V is loaded later, after P is stored)
    #pragma unroll
    for (int s = 0; s < 2; s++) {
        const int k0 = s * 32;
        const uint32_t st = sb + s * STAGE_B;
        #pragma unroll
        for (int p = 0; p < 4; p++) {
            CP_ASYNC(st + p * PART_B + r0c * 80 + c0c * 2, gp[p] + (size_t)r0c * QKH + k0 + c0c);
            CP_ASYNC(st + p * PART_B + (r0c + 64) * 80 + c0c * 2, gp[p] + (size_t)(r0c + 64) * QKH + k0 + c0c);
        }
        CP_COMMIT();
    }

    const int rA = lane & 15, gA = lane >> 4;
    const uint32_t aoff = (uint32_t)(((wm * 32 + rA) * SROW + gA * 8) * 2);
    const int rB = lane & 7, gB = lane >> 3;
    const uint32_t boff = (uint32_t)(((wn * 64 + (gB & 1) * 8 + rB) * SROW + (gB >> 1) * 8) * 2);

    float acc[2][8][4];
    #pragma unroll
    for (int i = 0; i < 2; i++)
        #pragma unroll
        for (int j = 0; j < 8; j++)
            #pragma unroll
            for (int k = 0; k < 4; k++) acc[i][j][k] = 0.f;

    for (int it = 0; it < 6; it++) {
        CP_WAIT1();
        __syncthreads();
        const uint32_t st = sb + (it & 1) * STAGE_B;
        const uint32_t sAh = st, sAl = st + PART_B, sBh = st + 2 * PART_B, sBl = st + 3 * PART_B;
        #pragma unroll
        for (int k2 = 0; k2 < 2; k2++) {
            const uint32_t ko = k2 * 32;
            uint32_t ah[2][4], al[2][4];
            #pragma unroll
            for (int mt = 0; mt < 2; mt++) {
                LDM_X4(ah[mt][0], ah[mt][1], ah[mt][2], ah[mt][3], sAh + aoff + mt * (16 * SROW * 2) + ko);
                LDM_X4(al[mt][0], al[mt][1], al[mt][2], al[mt][3], sAl + aoff + mt * (16 * SROW * 2) + ko);
            }
            #pragma unroll
            for (int ng = 0; ng < 4; ng++) {
                uint32_t bh2[4], bl2[4];
                LDM_X4(bh2[0], bh2[1], bh2[2], bh2[3], sBh + boff + ng * (16 * SROW * 2) + ko);
                LDM_X4(bl2[0], bl2[1], bl2[2], bl2[3], sBl + boff + ng * (16 * SROW * 2) + ko);
                #pragma unroll
                for (int mt = 0; mt < 2; mt++) {
                    #pragma unroll
                    for (int hh = 0; hh < 2; hh++) {
                        float* d = acc[mt][ng * 2 + hh];
                        MMA(d, ah[mt], bh2[hh], bh2[2 + hh]);
                        MMA(d, ah[mt], bl2[hh], bl2[2 + hh]);
                        MMA(d, al[mt], bh2[hh], bh2[2 + hh]);
                    }
                }
            }
        }
        __syncthreads();
        const int kn = it + 2;
        if (kn < 6) {
            const int k0 = kn * 32;
            const uint32_t s2 = sb + (it & 1) * STAGE_B;
            #pragma unroll
            for (int p = 0; p < 4; p++) {
                CP_ASYNC(s2 + p * PART_B + r0c * 80 + c0c * 2, gp[p] + (size_t)r0c * QKH + k0 + c0c);
                CP_ASYNC(s2 + p * PART_B + (r0c + 64) * 80 + c0c * 2, gp[p] + (size_t)(r0c + 64) * QKH + k0 + c0c);
            }
        }
        CP_COMMIT();
    }
    CP_WAIT0();
    __syncthreads();

    float* RMAX = (float*)(smem + REDOFF);
    float* RSUM = (float*)(smem + REDOFF + 1024);
    const float scl = 0.07216878364870323f;
    const int rbase = wm * 32 + (lane >> 2);
    const int cbase = wn * 64 + (lane & 3) * 2;

    #pragma unroll
    for (int mt = 0; mt < 2; mt++)
        #pragma unroll
        for (int nt = 0; nt < 8; nt++)
            #pragma unroll
            for (int k = 0; k < 4; k++) {
                const int r = rbase + mt * 16 + (k >> 1) * 8;
                const int c = cbase + nt * 8 + (k & 1);
                float v = acc[mt][nt][k] * scl;
                acc[mt][nt][k] = (c > r) ? -INFINITY : v;
            }

    #pragma unroll
    for (int mt = 0; mt < 2; mt++)
        #pragma unroll
        for (int hf = 0; hf < 2; hf++) {
            float m = -INFINITY;
            #pragma unroll
            for (int nt = 0; nt < 8; nt++)
                m = fmaxf(m, fmaxf(acc[mt][nt][hf * 2], acc[mt][nt][hf * 2 + 1]));
            m = fmaxf(m, __shfl_xor_sync(0xffffffffu, m, 1));
            m = fmaxf(m, __shfl_xor_sync(0xffffffffu, m, 2));
            if ((lane & 3) == 0) RMAX[wn * 128 + rbase + mt * 16 + hf * 8] = m;
        }
    __syncthreads();
    #pragma unroll
    for (int mt = 0; mt < 2; mt++)
        #pragma unroll
        for (int hf = 0; hf < 2; hf++) {
            const int r = rbase + mt * 16 + hf * 8;
            const float m = fmaxf(RMAX[r], RMAX[128 + r]);
            float s = 0.f;
            #pragma unroll
            for (int nt = 0; nt < 8; nt++) {
                float p0 = expf(acc[mt][nt][hf * 2] - m);
                float p1 = expf(acc[mt][nt][hf * 2 + 1] - m);
                acc[mt][nt][hf * 2] = p0; acc[mt][nt][hf * 2 + 1] = p1;
                s += p0 + p1;
            }
            s += __shfl_xor_sync(0xffffffffu, s, 1);
            s += __shfl_xor_sync(0xffffffffu, s, 2);
            if ((lane & 3) == 0) RSUM[wn * 128 + r] = s;
        }
    #pragma unroll
    for (int mt = 0; mt < 2; mt++)
        #pragma unroll
        for (int nt = 0; nt < 8; nt++)
            #pragma unroll
            for (int hf = 0; hf < 2; hf++) {
                const int r = rbase + mt * 16 + hf * 8;
                const int c = cbase + nt * 8;
                unsigned short h0, l0, h1, l1;
                split_bf16(acc[mt][nt][hf * 2], h0, l0);
                split_bf16(acc[mt][nt][hf * 2 + 1], h1, l1);
                *(uint32_t*)(smem + (r * PSTR + c) * 2) = h0 | ((uint32_t)h1 << 16);
                *(uint32_t*)(smem + PLBASE + (r * PSTR + c) * 2) = l0 | ((uint32_t)l1 << 16);
            }
    __syncthreads();

    // now (and only now) start streaming V into the dead QK stage-1 region
    #pragma unroll
    for (int s = 0; s < 2; s++) {
        const int k0 = s * 32;
        const uint32_t vst = sb + VBASE + s * 20480;
        CP_ASYNC(vst + r0c * 80 + c0c * 2, gvh + (size_t)r0c * SEQ + k0 + c0c);
        CP_ASYNC(vst + (r0c + 64) * 80 + c0c * 2, gvh + (size_t)(r0c + 64) * SEQ + k0 + c0c);
        CP_ASYNC(vst + 10240 + r0c * 80 + c0c * 2, gvl + (size_t)r0c * SEQ + k0 + c0c);
        CP_ASYNC(vst + 10240 + (r0c + 64) * 80 + c0c * 2, gvl + (size_t)(r0c + 64) * SEQ + k0 + c0c);
        CP_COMMIT();
    }

    const uint32_t aoffP = (uint32_t)(((wm * 32 + rA) * PSTR + gA * 8) * 2);
    float o[2][8][4];
    #pragma unroll
    for (int i = 0; i < 2; i++)
        #pragma unroll
        for (int j = 0; j < 8; j++)
            #pragma unroll
            for (int k = 0; k < 4; k++) o[i][j][k] = 0.f;

    for (int it = 0; it < 4; it++) {
        CP_WAIT1();
        __syncthreads();
        const uint32_t vst = sb + VBASE + (it & 1) * 20480;
        #pragma unroll
        for (int k2 = 0; k2 < 2; k2++) {
            const uint32_t kP = (it * 32 + k2 * 16) * 2;
            const uint32_t kV = k2 * 32;
            uint32_t ph[2][4], pl[2][4];
            #pragma unroll
            for (int mt = 0; mt < 2; mt++) {
                LDM_X4(ph[mt][0], ph[mt][1], ph[mt][2], ph[mt][3], sb + aoffP + mt * (16 * PSTR * 2) + kP);
                LDM_X4(pl[mt][0], pl[mt][1], pl[mt][2], pl[mt][3], sb + PLBASE + aoffP + mt * (16 * PSTR * 2) + kP);
            }
            #pragma unroll
            for (int ng = 0; ng < 4; ng++) {
                uint32_t vh[4], vl[4];
                LDM_X4(vh[0], vh[1], vh[2], vh[3], vst + boff + ng * (16 * SROW * 2) + kV);
                LDM_X4(vl[0], vl[1], vl[2], vl[3], vst + 10240 + boff + ng * (16 * SROW * 2) + kV);
                #pragma unroll
                for (int mt = 0; mt < 2; mt++) {
                    #pragma unroll
                    for (int hh = 0; hh < 2; hh++) {
                        float* d = o[mt][ng * 2 + hh];
                        MMA(d, ph[mt], vh[hh], vh[2 + hh]);
                        MMA(d, ph[mt], vl[hh], vl[2 + hh]);
                        MMA(d, pl[mt], vh[hh], vh[2 + hh]);
                    }
                }
            }
        }
        __syncthreads();
        const int kn = it + 2;
        if (kn < 4) {
            const int k0 = kn * 32;
            const uint32_t v2 = sb + VBASE + (it & 1) * 20480;
            CP_ASYNC(v2 + r0c * 80 + c0c * 2, gvh + (size_t)r0c * SEQ + k0 + c0c);
            CP_ASYNC(v2 + (r0c + 64) * 80 + c0c * 2, gvh + (size_t)(r0c + 64) * SEQ + k0 + c0c);
            CP_ASYNC(v2 + 10240 + r0c * 80 + c0c * 2, gvl + (size_t)r0c * SEQ + k0 + c0c);
            CP_ASYNC(v2 + 10240 + (r0c + 64) * 80 + c0c * 2, gvl + (size_t)(r0c + 64) * SEQ + k0 + c0c);
        }
        CP_COMMIT();
    }

    #pragma unroll
    for (int mt = 0; mt < 2; mt++) {
        float inv[2];
        #pragma unroll
        for (int hf = 0; hf < 2; hf++) {
            const int r = rbase + mt * 16 + hf * 8;
            inv[hf] = 1.f / (RSUM[r] + RSUM[128 + r]);
        }
        #pragma unroll
        for (int nt = 0; nt < 8; nt++) {
            const int c = cbase + nt * 8;
            #pragma unroll
            for (int hf = 0; hf < 2; hf++) {
                const int r = rbase + mt * 16 + hf * 8;
                const size_t off = (size_t)(b * SEQ + r) * DIM + h * VH + c;
                unsigned short h0, l0, h1, l1;
                split_bf16(o[mt][nt][hf * 2] * inv[hf], h0, l0);
                split_bf16(o[mt][nt][hf * 2 + 1] * inv[hf], h1, l1);
                *(uint32_t*)((unsigned short*)g_ao_h + off) = h0 | ((uint32_t)h1 << 16);
                *(uint32_t*)((unsigned short*)g_ao_l + off) = l0 | ((uint32_t)l1 << 16);
            }
        }
    }
}

// ---------------- launch ----------------
extern "C" void kernel_launch(void* const* d_in, const int* in_sizes, int n_in,
                              void* d_out, int out_size) {
    const float* x       = (const float*)d_in[0];
    const float* freqs   = (const float*)d_in[1];
    const float* wq_a    = (const float*)d_in[2];
    const float* q_norm  = (const float*)d_in[3];
    const float* wq_b    = (const float*)d_in[4];
    const float* wkv_a   = (const float*)d_in[5];
    const float* kv_norm = (const float*)d_in[6];
    const float* wkv_b   = (const float*)d_in[7];
    const float* wo      = (const float*)d_in[8];
    float* out = (float*)d_out;

    const int GEMM_SMEM = 2 * STAGE_B;
    cudaFuncSetAttribute(gemm_mma, cudaFuncAttributeMaxDynamicSharedMemorySize, GEMM_SMEM);
    cudaFuncSetAttribute(flash_attn, cudaFuncAttributeMaxDynamicSharedMemorySize, FLASH_SMEM);

    float *qkva, *out2;
    bf16 *xh, *xl, *qnh, *qnl, *kvnh, *kvnl, *aoh, *aol;
    bf16 *wch, *wcl, *wqbh, *wqbl, *wkvbh, *wkvbl, *woh, *wol;
    cudaGetSymbolAddress((void**)&qkva, g_qkva);
    cudaGetSymbolAddress((void**)&out2, g_out2);
    cudaGetSymbolAddress((void**)&xh,   g_x_h);   cudaGetSymbolAddress((void**)&xl,   g_x_l);
    cudaGetSymbolAddress((void**)&qnh,  g_qn_h);  cudaGetSymbolAddress((void**)&qnl,  g_qn_l);
    cudaGetSymbolAddress((void**)&kvnh, g_kvn_h); cudaGetSymbolAddress((void**)&kvnl, g_kvn_l);
    cudaGetSymbolAddress((void**)&aoh,  g_ao_h);  cudaGetSymbolAddress((void**)&aol,  g_ao_l);
    cudaGetSymbolAddress((void**)&wch,  g_wc_h);  cudaGetSymbolAddress((void**)&wcl,  g_wc_l);
    cudaGetSymbolAddress((void**)&wqbh,  g_wqbT_h);  cudaGetSymbolAddress((void**)&wqbl,  g_wqbT_l);
    cudaGetSymbolAddress((void**)&wkvbh, g_wkvbT_h); cudaGetSymbolAddress((void**)&wkvbl, g_wkvbT_l);
    cudaGetSymbolAddress((void**)&woh,   g_woT_h);   cudaGetSymbolAddress((void**)&wol,   g_woT_l);

    // #1-3 packs, #4 = gemm1 split-K2 (profiled slot)
    act_pack<<<NTOK * DIM / 4 / 256, 256>>>(x, xh, xl, NTOK * DIM);
    wt_pack2<<<dim3(QLORA / 32, DIM / 128), 256>>>(wq_a, wch, wcl, DIM, QLORA);
    wt_pack2<<<dim3(NKVP / 32, DIM / 128), 256>>>(wkv_a, wch + (size_t)QLORA * DIM, wcl + (size_t)QLORA * DIM, DIM, NKV);

    gemm_mma<<<dim3(NC1 / 128, NTOK / 128, 2), 256, GEMM_SMEM>>>(xh, xl, wch, wcl, qkva, NTOK, NC1, DIM, DIM / 2, 0);

    rmsnorm_pack<<<NTOK, 256>>>(qkva, q_norm, qnh, qnl, QLORA, NC1, NTOK * NC1);
    kv_post_pack<<<NTOK, 256>>>(kv_norm, freqs);
    wt_pack2<<<dim3(NQB / 32, QLORA / 128), 256>>>(wq_b, wqbh, wqbl, QLORA, NQB);
    wt_pack2<<<dim3(NKVB / 32, KVLORA / 128), 256>>>(wkv_b, wkvbh, wkvbl, KVLORA, NKVB);

    gemm_mma<<<dim3(NQB / 128, NTOK / 128), 256, GEMM_SMEM>>>(qnh, qnl, wqbh, wqbl, nullptr, NTOK, NQB, QLORA, QLORA, 1);
    gemm_mma<<<dim3(NKVB / 128, NTOK / 128), 256, GEMM_SMEM>>>(kvnh, kvnl, wkvbh, wkvbl, nullptr, NTOK, NKVB, KVLORA, KVLORA, 2);

    flash_attn<<<BATCH * NHEADS, 256, FLASH_SMEM>>>();

    wt_pack2<<<dim3(DIM / 32, DIM / 128), 256>>>(wo, woh, wol, DIM, DIM);
    gemm_mma<<<dim3(DIM / 128, NTOK / 128, 2), 256, GEMM_SMEM>>>(aoh, aol, woh, wol, out2, NTOK, DIM, DIM, DIM / 2, 0);
    add2<<<NTOK * DIM / 4 / 256, 256>>>(out2, out2 + (size_t)NTOK * DIM, out, NTOK * DIM);
}